// round 1
// baseline (speedup 1.0000x reference)
#include <cuda_runtime.h>
#include <math.h>

#define D 64
#define KD 32
#define MAXU 50000
#define MAXI 30000
#define MAXENT 100000
#define MAXE 500000
#define MAXEI 1000000
#define GAMMA 0.2f

// ---------------- scratch (device globals; no allocation) ----------------
__device__ float g_userWq[MAXU * D];
__device__ float g_itemWk[MAXI * D];
__device__ float g_itemWv[MAXI * D];
__device__ float g_scores[MAXEI];
__device__ float g_ex[MAXEI];
__device__ unsigned g_mkey[MAXU];
__device__ float g_den[MAXU];
__device__ float g_cntU[MAXU];
__device__ float g_itemCoeff[MAXI];
__device__ float g_pref[D];
__device__ float g_qc[D + 1];
__device__ float g_omega[MAXE];
__device__ float g_alphaA[MAXE];
__device__ float g_etaA[MAXE];
__device__ float g_segO[MAXENT];
__device__ float g_segE[MAXENT];
__device__ float g_cntH[MAXENT];
__device__ float g_eagg[MAXENT * D];
__device__ float g_uagg[MAXU * D];
__device__ float g_embA[MAXENT * D];
__device__ float g_embB[MAXENT * D];

// ---------------- helpers ----------------
__device__ __forceinline__ unsigned fkey(float f) {
    unsigned b = __float_as_uint(f);
    return (b & 0x80000000u) ? ~b : (b | 0x80000000u);
}
__device__ __forceinline__ float funkey(unsigned k) {
    return (k & 0x80000000u) ? __uint_as_float(k ^ 0x80000000u) : __uint_as_float(~k);
}
__device__ __forceinline__ float n2n(float x) {
    if (x != x) return 0.f;
    if (x == INFINITY) return 1e4f;
    if (x == -INFINITY) return 1e-4f;
    return x;
}
__device__ __forceinline__ float sigm(float x) { return 1.f / (1.f + expf(-x)); }

// ---------------- init kernels ----------------
__global__ void out_init_kernel(float4* out, const float4* ent, const float4* usr,
                                int ne16, int nu16) {
    int i = blockIdx.x * blockDim.x + threadIdx.x;
    if (i < ne16) out[i] = ent[i];
    else if (i < ne16 + nu16) out[i] = usr[i - ne16];
}
__global__ void init_users_kernel(unsigned* mkey, float* den, float* cnt, int n) {
    int i = blockIdx.x * blockDim.x + threadIdx.x;
    if (i < n) { mkey[i] = 0x007FFFFFu; den[i] = 0.f; cnt[i] = 0.f; }
}
__global__ void init_items_kernel(float* ic, int n) {
    int i = blockIdx.x * blockDim.x + threadIdx.x;
    if (i < n) ic[i] = 0.f;
}
__global__ void init_ent_kernel(float* a, float* b, float* c, int n) {
    int i = blockIdx.x * blockDim.x + threadIdx.x;
    if (i < n) { a[i] = 0.f; b[i] = 0.f; c[i] = 0.f; }
}
__global__ void init_small_kernel(float* pref, float* qc) {
    int i = threadIdx.x;
    if (i < D) pref[i] = 0.f;
    if (i < D + 1) qc[i] = 0.f;
}
__global__ void zero_agg_kernel(float4* ea, float4* ua, int ne4, int nu4) {
    int i = blockIdx.x * blockDim.x + threadIdx.x;
    float4 z = make_float4(0.f, 0.f, 0.f, 0.f);
    if (i < ne4) ea[i] = z;
    if (i < nu4) ua[i] = z;
}

// ---------------- small GEMM: Y[n,64] = X[n,64] @ W[64,64] ----------------
__global__ void gemm64_kernel(const float* __restrict__ X, const float* __restrict__ W,
                              float* __restrict__ Y, int nrows) {
    __shared__ float sW[64 * 64];
    __shared__ float sX[4 * 64];
    int tid = threadIdx.x;
    for (int i = tid; i < 4096; i += 256) sW[i] = W[i];
    int r = tid >> 6, j = tid & 63;
    int row = blockIdx.x * 4 + r;
    if (row < nrows) sX[r * 64 + j] = X[row * 64 + j];
    __syncthreads();
    if (row < nrows) {
        float acc = 0.f;
#pragma unroll
        for (int k = 0; k < 64; k++) acc += sX[r * 64 + k] * sW[k * 64 + j];
        Y[row * 64 + j] = acc;
    }
}

// ---------------- miner: scores + segment max ----------------
__global__ void score_kernel(const float* __restrict__ uq, const float* __restrict__ ik,
                             const int* __restrict__ users, const int* __restrict__ items,
                             const float* __restrict__ w, float* __restrict__ scores,
                             unsigned* mkey, int EI) {
    int g = blockIdx.x * blockDim.x + threadIdx.x;
    int e = g >> 5, lane = g & 31;
    if (e >= EI) return;
    int u = users[e], it = items[e];
    float2 q = ((const float2*)uq)[u * 32 + lane];
    float2 k = ((const float2*)ik)[it * 32 + lane];
    float p = q.x * k.x + q.y * k.y;
#pragma unroll
    for (int o = 16; o; o >>= 1) p += __shfl_xor_sync(0xffffffffu, p, o);
    if (lane == 0) {
        float s = p * 0.125f * w[e];
        scores[e] = s;
        atomicMax(&mkey[u], fkey(s));
    }
}

__global__ void exp_kernel(const float* __restrict__ scores, const int* __restrict__ users,
                           const unsigned* __restrict__ mkey, float* __restrict__ ex,
                           float* den, float* cnt, int EI) {
    int e = blockIdx.x * blockDim.x + threadIdx.x;
    if (e >= EI) return;
    int u = users[e];
    float m = funkey(mkey[u]);
    float v = expf(scores[e] - m);
    ex[e] = v;
    atomicAdd(&den[u], v);
    atomicAdd(&cnt[u], 1.f);
}

__global__ void coeff_kernel(const float* __restrict__ ex, const int* __restrict__ users,
                             const int* __restrict__ items, const float* __restrict__ den,
                             const float* __restrict__ cnt, float* itemCoeff, int EI) {
    int e = blockIdx.x * blockDim.x + threadIdx.x;
    if (e >= EI) return;
    int u = users[e];
    float c = ex[e] / (den[u] * fmaxf(cnt[u], 1.f));
    atomicAdd(&itemCoeff[items[e]], c);
}

__global__ void pref_kernel(const float* __restrict__ itemCoeff,
                            const float* __restrict__ itemWv, float* pref, int NI) {
    int j = threadIdx.x;  // 64 threads
    float acc = 0.f;
    for (int i = blockIdx.x; i < NI; i += gridDim.x)
        acc += itemCoeff[i] * itemWv[i * 64 + j];
    atomicAdd(&pref[j], acc);
}

// qc[j] = (rt_W2[j,:] . pref)/8 ; qc[64] = (rt_b2 . pref)/8
__global__ void qc_kernel(const float* __restrict__ rtW2, const float* __restrict__ rtb2,
                          const float* __restrict__ pref, float* qc) {
    __shared__ float sp[64];
    __shared__ float red[64];
    int j = threadIdx.x;
    sp[j] = pref[j];
    __syncthreads();
    float q = 0.f;
#pragma unroll
    for (int k = 0; k < 64; k++) q += rtW2[j * 64 + k] * sp[k];
    qc[j] = q * 0.125f;
    red[j] = rtb2[j] * sp[j];
    __syncthreads();
    if (j == 0) {
        float c = 0.f;
        for (int k = 0; k < 64; k++) c += red[k];
        qc[64] = c * 0.125f;
    }
}

// ---------------- fused fact-semantic + router -> omega ----------------
__device__ __forceinline__ void accrow(float f[64], const float* wr, float v) {
#pragma unroll
    for (int jj = 0; jj < 16; jj++) {
        float4 wv = ((const float4*)wr)[jj];
        f[4 * jj + 0] += v * wv.x;
        f[4 * jj + 1] += v * wv.y;
        f[4 * jj + 2] += v * wv.z;
        f[4 * jj + 3] += v * wv.w;
    }
}

// shared layout (floats): sW1[12288] @0, sRt1T[4096] @12288, srb1[64] @16384,
// sb1[64] @16448, sW2[192] @16512, sb2[3] @16704, sq[64] @16707, sc0 @16771
#define SMEM_OMEGA_FLOATS 16772

__global__ void omega_kernel(const float* __restrict__ ent_real, const float* __restrict__ ent_imag,
                             const float* __restrict__ rel_real, const float* __restrict__ rel_imag,
                             const int* __restrict__ eh, const int* __restrict__ et,
                             const int* __restrict__ etype,
                             const float* __restrict__ fpW1, const float* __restrict__ fpb1,
                             const float* __restrict__ fpW2, const float* __restrict__ fpb2,
                             const float* __restrict__ rtW1, const float* __restrict__ rtb1,
                             const float* __restrict__ qc,
                             float* __restrict__ omega, float* segO, float* cntH, int E) {
    extern __shared__ float sm[];
    float* sW1 = sm;
    float* sRt1T = sm + 12288;
    float* srb1 = sm + 16384;
    float* sb1 = sm + 16448;
    float* sW2 = sm + 16512;
    float* sb2 = sm + 16704;
    float* sq = sm + 16707;
    float* sc0 = sm + 16771;
    int tid = threadIdx.x;
    int bd = blockDim.x;
    for (int i = tid; i < 12288; i += bd) sW1[i] = fpW1[i];
    for (int i = tid; i < 4096; i += bd) {
        int k = i >> 6, j = i & 63;
        sRt1T[j * 64 + k] = rtW1[i];
    }
    for (int i = tid; i < 64; i += bd) {
        srb1[i] = rtb1[i];
        sb1[i] = fpb1[i];
        sq[i] = qc[i];
    }
    for (int i = tid; i < 192; i += bd) sW2[i] = fpW2[i];
    if (tid < 3) sb2[tid] = fpb2[tid];
    if (tid == 0) sc0[0] = qc[64];
    __syncthreads();

    int e = blockIdx.x * blockDim.x + tid;
    if (e >= E) return;
    int h = eh[e], t = et[e], r = etype[e] - 1;

    float f[64];
#pragma unroll
    for (int j = 0; j < 64; j++) f[j] = sb1[j];

    // layer 1: hid = feat @ W1 + b1, feat = [hr,hi,rr,ri,tr,ti]
    for (int s = 0; s < 6; s++) {
        int rowi = (s < 2) ? h : ((s < 4) ? r : t);
        const float* tb;
        if (s == 0 || s == 4) tb = ent_real;
        else if (s == 1 || s == 5) tb = ent_imag;
        else if (s == 2) tb = rel_real;
        else tb = rel_imag;
        const float4* p = (const float4*)(tb + (size_t)rowi * KD);
        for (int kk = 0; kk < 8; kk++) {
            float4 v = p[kk];
            const float* wr = sW1 + ((s * 8 + kk) * 4) * 64;
            accrow(f, wr, v.x);
            accrow(f, wr + 64, v.y);
            accrow(f, wr + 128, v.z);
            accrow(f, wr + 192, v.w);
        }
    }
#pragma unroll
    for (int j = 0; j < 64; j++) f[j] = sigm(f[j]);

    // layer 2 + softmax(3)
    float z0 = sb2[0], z1 = sb2[1], z2 = sb2[2];
#pragma unroll
    for (int j = 0; j < 64; j++) {
        float hv = f[j];
        z0 += hv * sW2[j * 3 + 0];
        z1 += hv * sW2[j * 3 + 1];
        z2 += hv * sW2[j * 3 + 2];
    }
    float mx = fmaxf(z0, fmaxf(z1, z2));
    float e0 = expf(z0 - mx), e1 = expf(z1 - mx), e2 = expf(z2 - mx);
    float inv = 1.f / (e0 + e1 + e2);
    float w0 = e0 * inv, w1 = e1 * inv, w2 = e2 * inv;

    // fact = [w0*hr + w1*rr + w2*tr, w0*hi + w1*ri + w2*ti]  (reuse f[])
    {
        const float4* phr = (const float4*)(ent_real + (size_t)h * KD);
        const float4* phi = (const float4*)(ent_imag + (size_t)h * KD);
        const float4* prr = (const float4*)(rel_real + (size_t)r * KD);
        const float4* pri = (const float4*)(rel_imag + (size_t)r * KD);
        const float4* ptr_ = (const float4*)(ent_real + (size_t)t * KD);
        const float4* pti = (const float4*)(ent_imag + (size_t)t * KD);
#pragma unroll
        for (int q = 0; q < 8; q++) {
            float4 a = phr[q], b = prr[q], c = ptr_[q];
            f[4 * q + 0] = w0 * a.x + w1 * b.x + w2 * c.x;
            f[4 * q + 1] = w0 * a.y + w1 * b.y + w2 * c.y;
            f[4 * q + 2] = w0 * a.z + w1 * b.z + w2 * c.z;
            f[4 * q + 3] = w0 * a.w + w1 * b.w + w2 * c.w;
            float4 ai = phi[q], bi = pri[q], ci = pti[q];
            f[32 + 4 * q + 0] = w0 * ai.x + w1 * bi.x + w2 * ci.x;
            f[32 + 4 * q + 1] = w0 * ai.y + w1 * bi.y + w2 * ci.y;
            f[32 + 4 * q + 2] = w0 * ai.z + w1 * bi.z + w2 * ci.z;
            f[32 + 4 * q + 3] = w0 * ai.w + w1 * bi.w + w2 * ci.w;
        }
    }

    // router: omega = c0 + sum_j sigmoid(rb1[j] + fact . rt_W1[:,j]) * q[j]
    float om = sc0[0];
    for (int j = 0; j < 64; j++) {
        float s = srb1[j];
        const float4* rp = (const float4*)(sRt1T + j * 64);
#pragma unroll
        for (int kk = 0; kk < 16; kk++) {
            float4 wv = rp[kk];
            s += f[4 * kk + 0] * wv.x + f[4 * kk + 1] * wv.y +
                 f[4 * kk + 2] * wv.z + f[4 * kk + 3] * wv.w;
        }
        om += sq[j] * sigm(s);
    }
    omega[e] = om;
    atomicAdd(&segO[h], om);
    atomicAdd(&cntH[h], 1.f);
}

// ---------------- alpha / eta ----------------
__global__ void alpha_kernel(const float* __restrict__ omega, const int* __restrict__ eh,
                             const float* __restrict__ segO, float* __restrict__ alpha,
                             float* __restrict__ eta, float* segE, int E) {
    int e = blockIdx.x * blockDim.x + threadIdx.x;
    if (e >= E) return;
    int h = eh[e];
    float a = omega[e] / (segO[h] + 1e-8f);
    alpha[e] = a;
    float e0 = (a > GAMMA) ? a : 0.f;
    eta[e] = e0;
    atomicAdd(&segE[h], e0);
}
__global__ void etanorm_kernel(const int* __restrict__ eh, const float* __restrict__ segE,
                               float* __restrict__ eta, int E) {
    int e = blockIdx.x * blockDim.x + threadIdx.x;
    if (e >= E) return;
    eta[e] = eta[e] / (segE[eh[e]] + 1e-8f);
}

// ---------------- graph conv scatters ----------------
__global__ void escatter_kernel(const float* __restrict__ src, const float* __restrict__ relemb,
                                const int* __restrict__ eh, const int* __restrict__ et,
                                const int* __restrict__ etype, const float* __restrict__ rho,
                                float* eagg, int E) {
    int idx = blockIdx.x * blockDim.x + threadIdx.x;
    int e = idx >> 4, q = idx & 15;
    if (e >= E) return;
    int h = eh[e], t = et[e], r = etype[e] - 1;
    float rv = rho[e];
    float4 x = ((const float4*)src)[t * 16 + q];
    float4 rr = ((const float4*)relemb)[r * 16 + q];
    float* base = eagg + (size_t)h * 64 + q * 4;
    atomicAdd(base + 0, rv * x.x * rr.x);
    atomicAdd(base + 1, rv * x.y * rr.y);
    atomicAdd(base + 2, rv * x.z * rr.z);
    atomicAdd(base + 3, rv * x.w * rr.w);
}

__global__ void uscatter_kernel(const float* __restrict__ src, const int* __restrict__ users,
                                const int* __restrict__ items, const float* __restrict__ w,
                                float* uagg, int EI) {
    int idx = blockIdx.x * blockDim.x + threadIdx.x;
    int e = idx >> 4, q = idx & 15;
    if (e >= EI) return;
    int u = users[e], it = items[e];
    float wv = w[e];
    float4 x = ((const float4*)src)[it * 16 + q];
    float* base = uagg + (size_t)u * 64 + q * 4;
    atomicAdd(base + 0, wv * x.x);
    atomicAdd(base + 1, wv * x.y);
    atomicAdd(base + 2, wv * x.z);
    atomicAdd(base + 3, wv * x.w);
}

// ---------------- normalize + accumulate ----------------
__global__ void enorm_kernel(const float* __restrict__ eagg, const float* __restrict__ cntH,
                             float* __restrict__ dst, float* __restrict__ out, int n) {
    int g = blockIdx.x * blockDim.x + threadIdx.x;
    int row = g >> 5, lane = g & 31;
    if (row >= n) return;
    float2 v = ((const float2*)eagg)[row * 32 + lane];
    float c = fmaxf(cntH[row], 1.f);
    v.x /= c;
    v.y /= c;
    float ss = v.x * v.x + v.y * v.y;
#pragma unroll
    for (int o = 16; o; o >>= 1) ss += __shfl_xor_sync(0xffffffffu, ss, o);
    float inv = 1.f / fmaxf(sqrtf(ss), 1e-8f);
    float a = n2n(v.x * inv), b = n2n(v.y * inv);
    ((float2*)dst)[row * 32 + lane] = make_float2(a, b);
    float2 o2 = ((float2*)out)[row * 32 + lane];
    o2.x += a;
    o2.y += b;
    ((float2*)out)[row * 32 + lane] = o2;
}

__global__ void unorm_kernel(const float* __restrict__ uagg, float* __restrict__ out, int n) {
    int g = blockIdx.x * blockDim.x + threadIdx.x;
    int row = g >> 5, lane = g & 31;
    if (row >= n) return;
    float2 v = ((const float2*)uagg)[row * 32 + lane];
    float ss = v.x * v.x + v.y * v.y;
#pragma unroll
    for (int o = 16; o; o >>= 1) ss += __shfl_xor_sync(0xffffffffu, ss, o);
    float inv = 1.f / fmaxf(sqrtf(ss), 1e-8f);
    float a = n2n(v.x * inv), b = n2n(v.y * inv);
    float2 o2 = ((float2*)out)[row * 32 + lane];
    o2.x += a;
    o2.y += b;
    ((float2*)out)[row * 32 + lane] = o2;
}

// ---------------- launch ----------------
extern "C" void kernel_launch(void* const* d_in, const int* in_sizes, int n_in,
                              void* d_out, int out_size) {
    const float* user_embed = (const float*)d_in[0];
    const float* item_embed = (const float*)d_in[1];
    const float* Wq = (const float*)d_in[2];
    const float* Wk = (const float*)d_in[3];
    const float* Wv = (const float*)d_in[4];
    const float* ent_real = (const float*)d_in[5];
    const float* ent_imag = (const float*)d_in[6];
    const float* rel_real = (const float*)d_in[7];
    const float* rel_imag = (const float*)d_in[8];
    const float* fp_W1 = (const float*)d_in[9];
    const float* fp_b1 = (const float*)d_in[10];
    const float* fp_W2 = (const float*)d_in[11];
    const float* fp_b2 = (const float*)d_in[12];
    const float* rt_W1 = (const float*)d_in[13];
    const float* rt_b1 = (const float*)d_in[14];
    const float* rt_W2 = (const float*)d_in[15];
    const float* rt_b2 = (const float*)d_in[16];
    const float* relation_emb = (const float*)d_in[17];
    const float* user_emb = (const float*)d_in[18];
    const float* entity_emb = (const float*)d_in[19];
    const float* inter_edge_w = (const float*)d_in[20];
    const int* edge_index = (const int*)d_in[21];
    const int* edge_type = (const int*)d_in[22];
    const int* inter_edge = (const int*)d_in[23];
    float* out = (float*)d_out;

    int NU = in_sizes[0] / D;
    int NI = in_sizes[1] / D;
    int NE = in_sizes[5] / KD;
    int E = in_sizes[22];
    int EI = in_sizes[20];
    const int* eh = edge_index;
    const int* et = edge_index + E;
    const int* users = inter_edge;
    const int* items = inter_edge + EI;

    // scratch symbol addresses
    float *userWq, *itemWk, *itemWv, *scores, *ex, *den, *cntU, *itemCoeff, *pref, *qc;
    float *omega, *alphaA, *etaA, *segO, *segE, *cntH, *eagg, *uagg, *embA, *embB;
    unsigned* mkey;
    cudaGetSymbolAddress((void**)&userWq, g_userWq);
    cudaGetSymbolAddress((void**)&itemWk, g_itemWk);
    cudaGetSymbolAddress((void**)&itemWv, g_itemWv);
    cudaGetSymbolAddress((void**)&scores, g_scores);
    cudaGetSymbolAddress((void**)&ex, g_ex);
    cudaGetSymbolAddress((void**)&mkey, g_mkey);
    cudaGetSymbolAddress((void**)&den, g_den);
    cudaGetSymbolAddress((void**)&cntU, g_cntU);
    cudaGetSymbolAddress((void**)&itemCoeff, g_itemCoeff);
    cudaGetSymbolAddress((void**)&pref, g_pref);
    cudaGetSymbolAddress((void**)&qc, g_qc);
    cudaGetSymbolAddress((void**)&omega, g_omega);
    cudaGetSymbolAddress((void**)&alphaA, g_alphaA);
    cudaGetSymbolAddress((void**)&etaA, g_etaA);
    cudaGetSymbolAddress((void**)&segO, g_segO);
    cudaGetSymbolAddress((void**)&segE, g_segE);
    cudaGetSymbolAddress((void**)&cntH, g_cntH);
    cudaGetSymbolAddress((void**)&eagg, g_eagg);
    cudaGetSymbolAddress((void**)&uagg, g_uagg);
    cudaGetSymbolAddress((void**)&embA, g_embA);
    cudaGetSymbolAddress((void**)&embB, g_embB);

    // init output and accumulators
    {
        int tot = (NE + NU) * 16;
        out_init_kernel<<<(tot + 255) / 256, 256>>>((float4*)out, (const float4*)entity_emb,
                                                    (const float4*)user_emb, NE * 16, NU * 16);
    }
    init_users_kernel<<<(NU + 255) / 256, 256>>>(mkey, den, cntU, NU);
    init_items_kernel<<<(NI + 255) / 256, 256>>>(itemCoeff, NI);
    init_ent_kernel<<<(NE + 255) / 256, 256>>>(segO, segE, cntH, NE);
    init_small_kernel<<<1, 128>>>(pref, qc);

    // ---- attention preference miner ----
    gemm64_kernel<<<(NU + 3) / 4, 256>>>(user_embed, Wq, userWq, NU);
    gemm64_kernel<<<(NI + 3) / 4, 256>>>(item_embed, Wk, itemWk, NI);
    gemm64_kernel<<<(NI + 3) / 4, 256>>>(item_embed, Wv, itemWv, NI);
    {
        long long th = (long long)EI * 32;
        score_kernel<<<(int)((th + 255) / 256), 256>>>(userWq, itemWk, users, items,
                                                       inter_edge_w, scores, mkey, EI);
    }
    exp_kernel<<<(EI + 255) / 256, 256>>>(scores, users, mkey, ex, den, cntU, EI);
    coeff_kernel<<<(EI + 255) / 256, 256>>>(ex, users, items, den, cntU, itemCoeff, EI);
    pref_kernel<<<256, 64>>>(itemCoeff, itemWv, pref, NI);
    qc_kernel<<<1, 64>>>(rt_W2, rt_b2, pref, qc);

    // ---- fused fact-semantic + router ----
    int smem_bytes = SMEM_OMEGA_FLOATS * 4;
    cudaFuncSetAttribute(omega_kernel, cudaFuncAttributeMaxDynamicSharedMemorySize, smem_bytes);
    omega_kernel<<<(E + 127) / 128, 128, smem_bytes>>>(
        ent_real, ent_imag, rel_real, rel_imag, eh, et, edge_type,
        fp_W1, fp_b1, fp_W2, fp_b2, rt_W1, rt_b1, qc, omega, segO, cntH, E);

    alpha_kernel<<<(E + 255) / 256, 256>>>(omega, eh, segO, alphaA, etaA, segE, E);
    etanorm_kernel<<<(E + 255) / 256, 256>>>(eh, segE, etaA, E);

    // ---- 3-hop graph conv ----
    const float* srcs[3] = {entity_emb, embA, embB};
    float* dsts[3] = {embA, embB, embA};
    const float* rhos[3] = {alphaA, alphaA, etaA};
    for (int hop = 0; hop < 3; hop++) {
        int z4 = NE * 16;
        zero_agg_kernel<<<(z4 + 255) / 256, 256>>>((float4*)eagg, (float4*)uagg, NE * 16, NU * 16);
        {
            long long th = (long long)E * 16;
            escatter_kernel<<<(int)((th + 255) / 256), 256>>>(srcs[hop], relation_emb, eh, et,
                                                              edge_type, rhos[hop], eagg, E);
        }
        {
            long long th = (long long)EI * 16;
            uscatter_kernel<<<(int)((th + 255) / 256), 256>>>(srcs[hop], users, items,
                                                              inter_edge_w, uagg, EI);
        }
        {
            long long th = (long long)NE * 32;
            enorm_kernel<<<(int)((th + 255) / 256), 256>>>(eagg, cntH, dsts[hop], out, NE);
        }
        {
            long long th = (long long)NU * 32;
            unorm_kernel<<<(int)((th + 255) / 256), 256>>>(uagg, out + (size_t)NE * D, NU);
        }
    }
}

// round 2
// speedup vs baseline: 1.1816x; 1.1816x over previous
#include <cuda_runtime.h>
#include <math.h>

#define D 64
#define KD 32
#define MAXU 50000
#define MAXI 30000
#define MAXENT 100000
#define MAXE 500000
#define MAXEI 1000000
#define GAMMA 0.2f

typedef unsigned long long u64;

// ---------------- scratch (device globals; no allocation) ----------------
__device__ float g_userWq[MAXU * D];
__device__ float g_itemWk[MAXI * D];
__device__ float g_itemWv[MAXI * D];
__device__ float g_scores[MAXEI];
__device__ float g_itemCoeff[MAXI];
__device__ float g_pref[D];
__device__ float g_qc[D + 1];
__device__ float g_omega[MAXE];
__device__ float g_alphaA[MAXE];
__device__ float g_etaA[MAXE];
__device__ float g_embA[MAXENT * D];
__device__ float g_embB[MAXENT * D];
__device__ int g_degE[MAXENT];
__device__ int g_rowE[MAXENT + 1];
__device__ int g_curE[MAXENT];
__device__ int g_csrE[MAXE];
__device__ int g_degU[MAXU];
__device__ int g_rowU[MAXU + 1];
__device__ int g_curU[MAXU];
__device__ int g_csrU[MAXEI];

// ---------------- helpers ----------------
__device__ __forceinline__ float n2n(float x) {
    if (x != x) return 0.f;
    if (x == INFINITY) return 1e4f;
    if (x == -INFINITY) return 1e-4f;
    return x;
}
__device__ __forceinline__ float sigm(float x) { return 1.f / (1.f + expf(-x)); }

__device__ __forceinline__ u64 pack2(float x, float y) {
    u64 r;
    asm("mov.b64 %0, {%1, %2};" : "=l"(r) : "f"(x), "f"(y));
    return r;
}
__device__ __forceinline__ float2 unpack2(u64 v) {
    float2 r;
    asm("mov.b64 {%0, %1}, %2;" : "=f"(r.x), "=f"(r.y) : "l"(v));
    return r;
}
__device__ __forceinline__ u64 ffma2(u64 a, u64 b, u64 c) {
    u64 d;
    asm("fma.rn.f32x2 %0, %1, %2, %3;" : "=l"(d) : "l"(a), "l"(b), "l"(c));
    return d;
}

// ---------------- init / CSR build ----------------
__global__ void out_init_kernel(float4* out, const float4* ent, const float4* usr,
                                int ne16, int nu16) {
    int i = blockIdx.x * blockDim.x + threadIdx.x;
    if (i < ne16) out[i] = ent[i];
    else if (i < ne16 + nu16) out[i] = usr[i - ne16];
}

__global__ void zero_kernel(int* degE, int* degU, float* ic, float* pref,
                            int NE, int NU, int NI) {
    int i = blockIdx.x * blockDim.x + threadIdx.x;
    if (i < NE) degE[i] = 0;
    if (i < NU) degU[i] = 0;
    if (i < NI) ic[i] = 0.f;
    if (i < 64) pref[i] = 0.f;
}

__global__ void hist_kernel(const int* __restrict__ idx, int* deg, int n) {
    int i = blockIdx.x * blockDim.x + threadIdx.x;
    if (i < n) atomicAdd(&deg[idx[i]], 1);
}

// single-block exclusive scan (n up to ~100k)
__global__ void exscan_kernel(const int* __restrict__ deg, int* row, int n) {
    __shared__ int sh_carry;
    __shared__ int wsum[32];
    int tid = threadIdx.x, lane = tid & 31, wid = tid >> 5;
    if (tid == 0) sh_carry = 0;
    __syncthreads();
    for (int base = 0; base < n; base += blockDim.x) {
        int i = base + tid;
        int v = (i < n) ? deg[i] : 0;
        int s = v;
#pragma unroll
        for (int o = 1; o < 32; o <<= 1) {
            int t = __shfl_up_sync(0xffffffffu, s, o);
            if (lane >= o) s += t;
        }
        if (lane == 31) wsum[wid] = s;
        __syncthreads();
        if (wid == 0) {
            int ws = wsum[lane];
#pragma unroll
            for (int o = 1; o < 32; o <<= 1) {
                int t = __shfl_up_sync(0xffffffffu, ws, o);
                if (lane >= o) ws += t;
            }
            wsum[lane] = ws;
        }
        __syncthreads();
        int woff = (wid == 0) ? 0 : wsum[wid - 1];
        int excl = sh_carry + woff + s - v;
        if (i < n) row[i] = excl;
        int blocktot = wsum[(blockDim.x >> 5) - 1];
        __syncthreads();
        if (tid == 0) sh_carry += blocktot;
        __syncthreads();
    }
    if (threadIdx.x == 0) row[n] = sh_carry;
}

__global__ void copy_int_kernel(const int* __restrict__ a, int* b, int n) {
    int i = blockIdx.x * blockDim.x + threadIdx.x;
    if (i < n) b[i] = a[i];
}

__global__ void fill_kernel(const int* __restrict__ idx, int* cur, int* csr, int n) {
    int e = blockIdx.x * blockDim.x + threadIdx.x;
    if (e < n) {
        int p = atomicAdd(&cur[idx[e]], 1);
        csr[p] = e;
    }
}

// ---------------- small GEMM: Y[n,64] = X[n,64] @ W[64,64] ----------------
__global__ void gemm64_kernel(const float* __restrict__ X, const float* __restrict__ W,
                              float* __restrict__ Y, int nrows) {
    __shared__ float sW[64 * 64];
    __shared__ float sX[16 * 64];
    int tid = threadIdx.x;
    for (int i = tid; i < 4096; i += 1024) sW[i] = W[i];
    int r = tid >> 6, j = tid & 63;
    int row = blockIdx.x * 16 + r;
    if (row < nrows) sX[r * 64 + j] = X[row * 64 + j];
    __syncthreads();
    if (row < nrows) {
        float acc = 0.f;
#pragma unroll
        for (int k = 0; k < 64; k++) acc += sX[r * 64 + k] * sW[k * 64 + j];
        Y[row * 64 + j] = acc;
    }
}

// ---------------- miner ----------------
__global__ void score_kernel(const float* __restrict__ uq, const float* __restrict__ ik,
                             const int* __restrict__ users, const int* __restrict__ items,
                             const float* __restrict__ w, float* __restrict__ scores, int EI) {
    int g = blockIdx.x * blockDim.x + threadIdx.x;
    int e = g >> 5, lane = g & 31;
    if (e >= EI) return;
    int u = users[e], it = items[e];
    float2 q = ((const float2*)uq)[u * 32 + lane];
    float2 k = ((const float2*)ik)[it * 32 + lane];
    float p = q.x * k.x + q.y * k.y;
#pragma unroll
    for (int o = 16; o; o >>= 1) p += __shfl_xor_sync(0xffffffffu, p, o);
    if (lane == 0) scores[e] = p * 0.125f * w[e];
}

// warp per user: softmax over its edges, scatter coeff to items
__global__ void usoftmax_kernel(const float* __restrict__ scores, const int* __restrict__ items,
                                const int* __restrict__ rowU, const int* __restrict__ csrU,
                                float* itemCoeff, int NU) {
    int g = blockIdx.x * blockDim.x + threadIdx.x;
    int u = g >> 5, lane = g & 31;
    if (u >= NU) return;
    int s = rowU[u], e = rowU[u + 1];
    int deg = e - s;
    if (deg == 0) return;
    float m = -INFINITY;
    for (int i = s + lane; i < e; i += 32) m = fmaxf(m, scores[csrU[i]]);
#pragma unroll
    for (int o = 16; o; o >>= 1) m = fmaxf(m, __shfl_xor_sync(0xffffffffu, m, o));
    float den = 0.f;
    for (int i = s + lane; i < e; i += 32) den += expf(scores[csrU[i]] - m);
#pragma unroll
    for (int o = 16; o; o >>= 1) den += __shfl_xor_sync(0xffffffffu, den, o);
    float invc = 1.f / (den * fmaxf((float)deg, 1.f));
    for (int i = s + lane; i < e; i += 32) {
        int ed = csrU[i];
        atomicAdd(&itemCoeff[items[ed]], expf(scores[ed] - m) * invc);
    }
}

__global__ void pref_kernel(const float* __restrict__ itemCoeff,
                            const float* __restrict__ itemWv, float* pref, int NI) {
    int j = threadIdx.x;  // 64 threads
    float acc = 0.f;
    for (int i = blockIdx.x; i < NI; i += gridDim.x)
        acc += itemCoeff[i] * itemWv[i * 64 + j];
    atomicAdd(&pref[j], acc);
}

__global__ void qc_kernel(const float* __restrict__ rtW2, const float* __restrict__ rtb2,
                          const float* __restrict__ pref, float* qc) {
    __shared__ float sp[64];
    __shared__ float red[64];
    int j = threadIdx.x;
    sp[j] = pref[j];
    __syncthreads();
    float q = 0.f;
#pragma unroll
    for (int k = 0; k < 64; k++) q += rtW2[j * 64 + k] * sp[k];
    qc[j] = q * 0.125f;
    red[j] = rtb2[j] * sp[j];
    __syncthreads();
    if (j == 0) {
        float c = 0.f;
        for (int k = 0; k < 64; k++) c += red[k];
        qc[64] = c * 0.125f;
    }
}

// ---------------- fused fact-semantic + router -> omega (f32x2 packed) ----------------
__device__ __forceinline__ void rowacc(u64 acc[32], const float* wr, float v) {
    u64 vv = pack2(v, v);
    const ulonglong2* w2 = (const ulonglong2*)wr;
#pragma unroll
    for (int jj = 0; jj < 16; jj++) {
        ulonglong2 w = w2[jj];
        acc[2 * jj] = ffma2(vv, w.x, acc[2 * jj]);
        acc[2 * jj + 1] = ffma2(vv, w.y, acc[2 * jj + 1]);
    }
}

#define SMEM_OMEGA_FLOATS 16772

__global__ void omega_kernel(const float* __restrict__ ent_real, const float* __restrict__ ent_imag,
                             const float* __restrict__ rel_real, const float* __restrict__ rel_imag,
                             const int* __restrict__ eh, const int* __restrict__ et,
                             const int* __restrict__ etype,
                             const float* __restrict__ fpW1, const float* __restrict__ fpb1,
                             const float* __restrict__ fpW2, const float* __restrict__ fpb2,
                             const float* __restrict__ rtW1, const float* __restrict__ rtb1,
                             const float* __restrict__ qc,
                             float* __restrict__ omega, int E) {
    extern __shared__ float sm[];
    float* sW1 = sm;              // 12288
    float* sRt1T = sm + 12288;    // 4096
    float* srb1 = sm + 16384;     // 64
    float* sb1 = sm + 16448;      // 64
    float* sW2 = sm + 16512;      // 192
    float* sb2 = sm + 16704;      // 3
    float* sq = sm + 16707;       // 64
    float* sc0 = sm + 16771;      // 1
    int tid = threadIdx.x;
    int bd = blockDim.x;
    for (int i = tid; i < 12288; i += bd) sW1[i] = fpW1[i];
    for (int i = tid; i < 4096; i += bd) {
        int k = i >> 6, j = i & 63;
        sRt1T[j * 64 + k] = rtW1[i];
    }
    for (int i = tid; i < 64; i += bd) {
        srb1[i] = rtb1[i];
        sb1[i] = fpb1[i];
        sq[i] = qc[i];
    }
    for (int i = tid; i < 192; i += bd) sW2[i] = fpW2[i];
    if (tid < 3) sb2[tid] = fpb2[tid];
    if (tid == 0) sc0[0] = qc[64];
    __syncthreads();

    int e = blockIdx.x * blockDim.x + tid;
    if (e >= E) return;
    int h = eh[e], t = et[e], r = etype[e] - 1;

    u64 acc[32];
#pragma unroll
    for (int j = 0; j < 32; j++) acc[j] = ((const u64*)sb1)[j];

    // layer 1: hid = feat @ W1 + b1, feat = [hr,hi,rr,ri,tr,ti]
    for (int s = 0; s < 6; s++) {
        int rowi = (s < 2) ? h : ((s < 4) ? r : t);
        const float* tb;
        if (s == 0 || s == 4) tb = ent_real;
        else if (s == 1 || s == 5) tb = ent_imag;
        else if (s == 2) tb = rel_real;
        else tb = rel_imag;
        const float4* p = (const float4*)(tb + (size_t)rowi * KD);
#pragma unroll
        for (int kk = 0; kk < 8; kk++) {
            float4 v = p[kk];
            const float* wr = sW1 + ((s * 8 + kk) * 4) * 64;
            rowacc(acc, wr, v.x);
            rowacc(acc, wr + 64, v.y);
            rowacc(acc, wr + 128, v.z);
            rowacc(acc, wr + 192, v.w);
        }
    }

    // layer 2 + softmax(3)
    float z0 = sb2[0], z1 = sb2[1], z2 = sb2[2];
#pragma unroll
    for (int j = 0; j < 32; j++) {
        float2 hv = unpack2(acc[j]);
        float s0 = sigm(hv.x), s1 = sigm(hv.y);
        z0 += s0 * sW2[(2 * j) * 3 + 0] + s1 * sW2[(2 * j + 1) * 3 + 0];
        z1 += s0 * sW2[(2 * j) * 3 + 1] + s1 * sW2[(2 * j + 1) * 3 + 1];
        z2 += s0 * sW2[(2 * j) * 3 + 2] + s1 * sW2[(2 * j + 1) * 3 + 2];
    }
    float mx = fmaxf(z0, fmaxf(z1, z2));
    float e0 = expf(z0 - mx), e1 = expf(z1 - mx), e2 = expf(z2 - mx);
    float inv = 1.f / (e0 + e1 + e2);
    float w0 = e0 * inv, w1 = e1 * inv, w2 = e2 * inv;

    // fact = [w0*hr + w1*rr + w2*tr, w0*hi + w1*ri + w2*ti] packed pairs over k
    {
        const float2* phr = (const float2*)(ent_real + (size_t)h * KD);
        const float2* phi = (const float2*)(ent_imag + (size_t)h * KD);
        const float2* prr = (const float2*)(rel_real + (size_t)r * KD);
        const float2* pri = (const float2*)(rel_imag + (size_t)r * KD);
        const float2* ptr_ = (const float2*)(ent_real + (size_t)t * KD);
        const float2* pti = (const float2*)(ent_imag + (size_t)t * KD);
#pragma unroll
        for (int q = 0; q < 16; q++) {
            float2 a = phr[q], b = prr[q], c = ptr_[q];
            acc[q] = pack2(w0 * a.x + w1 * b.x + w2 * c.x,
                           w0 * a.y + w1 * b.y + w2 * c.y);
            float2 ai = phi[q], bi = pri[q], ci = pti[q];
            acc[16 + q] = pack2(w0 * ai.x + w1 * bi.x + w2 * ci.x,
                                w0 * ai.y + w1 * bi.y + w2 * ci.y);
        }
    }

    // router: omega = c0 + sum_j sigmoid(rb1[j] + fact . rt_W1[:,j]) * q[j]
    float om = sc0[0];
    for (int j = 0; j < 64; j++) {
        const ulonglong2* w2p = (const ulonglong2*)(sRt1T + j * 64);
        u64 p0 = 0, p1 = 0, p2 = 0, p3 = 0;
#pragma unroll
        for (int kk = 0; kk < 8; kk++) {
            ulonglong2 wa = w2p[2 * kk], wb = w2p[2 * kk + 1];
            p0 = ffma2(acc[4 * kk + 0], wa.x, p0);
            p1 = ffma2(acc[4 * kk + 1], wa.y, p1);
            p2 = ffma2(acc[4 * kk + 2], wb.x, p2);
            p3 = ffma2(acc[4 * kk + 3], wb.y, p3);
        }
        float2 q0 = unpack2(p0), q1 = unpack2(p1), q2 = unpack2(p2), q3 = unpack2(p3);
        float sdot = srb1[j] + (q0.x + q0.y) + (q1.x + q1.y) + (q2.x + q2.y) + (q3.x + q3.y);
        om += sq[j] * sigm(sdot);
    }
    omega[e] = om;
}

// ---------------- alpha / eta via CSR (thread per head row) ----------------
__global__ void alphaeta_kernel(const float* __restrict__ omega, const int* __restrict__ rowE,
                                const int* __restrict__ csrE, float* __restrict__ alpha,
                                float* __restrict__ eta, int NE) {
    int h = blockIdx.x * blockDim.x + threadIdx.x;
    if (h >= NE) return;
    int s = rowE[h], e = rowE[h + 1];
    if (s == e) return;
    float so = 0.f;
    for (int i = s; i < e; i++) so += omega[csrE[i]];
    float d1 = so + 1e-8f;
    float se = 0.f;
    for (int i = s; i < e; i++) {
        float a = omega[csrE[i]] / d1;
        se += (a > GAMMA) ? a : 0.f;
    }
    float d2 = se + 1e-8f;
    for (int i = s; i < e; i++) {
        int ed = csrE[i];
        float a = omega[ed] / d1;
        alpha[ed] = a;
        float e0 = (a > GAMMA) ? a : 0.f;
        eta[ed] = e0 / d2;
    }
}

// ---------------- fused hop kernels (gather + mean + normalize + out accum) ----------------
__global__ void ehop_kernel(const float* __restrict__ src, const float* __restrict__ relemb,
                            const int* __restrict__ et, const int* __restrict__ etype,
                            const float* __restrict__ rho, const int* __restrict__ rowE,
                            const int* __restrict__ csrE,
                            float* __restrict__ dst, float* __restrict__ out, int NE) {
    int g = blockIdx.x * blockDim.x + threadIdx.x;
    int h = g >> 5, lane = g & 31;
    if (h >= NE) return;
    int s = rowE[h], e = rowE[h + 1];
    float2 acc = make_float2(0.f, 0.f);
    for (int i = s; i < e; i++) {
        int ed = csrE[i];
        int t = et[ed];
        int r = etype[ed] - 1;
        float rv = rho[ed];
        float2 x = ((const float2*)src)[t * 32 + lane];
        float2 rr = ((const float2*)relemb)[r * 32 + lane];
        acc.x += rv * x.x * rr.x;
        acc.y += rv * x.y * rr.y;
    }
    float c = fmaxf((float)(e - s), 1.f);
    acc.x /= c;
    acc.y /= c;
    float ss = acc.x * acc.x + acc.y * acc.y;
#pragma unroll
    for (int o = 16; o; o >>= 1) ss += __shfl_xor_sync(0xffffffffu, ss, o);
    float inv = 1.f / fmaxf(sqrtf(ss), 1e-8f);
    float a = n2n(acc.x * inv), b = n2n(acc.y * inv);
    ((float2*)dst)[h * 32 + lane] = make_float2(a, b);
    float2 o2 = ((float2*)out)[h * 32 + lane];
    o2.x += a;
    o2.y += b;
    ((float2*)out)[h * 32 + lane] = o2;
}

__global__ void uhop_kernel(const float* __restrict__ src, const int* __restrict__ items,
                            const float* __restrict__ w, const int* __restrict__ rowU,
                            const int* __restrict__ csrU,
                            float* __restrict__ out, int NU) {
    int g = blockIdx.x * blockDim.x + threadIdx.x;
    int u = g >> 5, lane = g & 31;
    if (u >= NU) return;
    int s = rowU[u], e = rowU[u + 1];
    float2 acc = make_float2(0.f, 0.f);
    for (int i = s; i < e; i++) {
        int ed = csrU[i];
        int it = items[ed];
        float wv = w[ed];
        float2 x = ((const float2*)src)[it * 32 + lane];
        acc.x += wv * x.x;
        acc.y += wv * x.y;
    }
    float ss = acc.x * acc.x + acc.y * acc.y;
#pragma unroll
    for (int o = 16; o; o >>= 1) ss += __shfl_xor_sync(0xffffffffu, ss, o);
    float inv = 1.f / fmaxf(sqrtf(ss), 1e-8f);
    float a = n2n(acc.x * inv), b = n2n(acc.y * inv);
    float2 o2 = ((float2*)out)[u * 32 + lane];
    o2.x += a;
    o2.y += b;
    ((float2*)out)[u * 32 + lane] = o2;
}

// ---------------- launch ----------------
extern "C" void kernel_launch(void* const* d_in, const int* in_sizes, int n_in,
                              void* d_out, int out_size) {
    const float* user_embed = (const float*)d_in[0];
    const float* item_embed = (const float*)d_in[1];
    const float* Wq = (const float*)d_in[2];
    const float* Wk = (const float*)d_in[3];
    const float* Wv = (const float*)d_in[4];
    const float* ent_real = (const float*)d_in[5];
    const float* ent_imag = (const float*)d_in[6];
    const float* rel_real = (const float*)d_in[7];
    const float* rel_imag = (const float*)d_in[8];
    const float* fp_W1 = (const float*)d_in[9];
    const float* fp_b1 = (const float*)d_in[10];
    const float* fp_W2 = (const float*)d_in[11];
    const float* fp_b2 = (const float*)d_in[12];
    const float* rt_W1 = (const float*)d_in[13];
    const float* rt_b1 = (const float*)d_in[14];
    const float* rt_W2 = (const float*)d_in[15];
    const float* rt_b2 = (const float*)d_in[16];
    const float* relation_emb = (const float*)d_in[17];
    const float* user_emb = (const float*)d_in[18];
    const float* entity_emb = (const float*)d_in[19];
    const float* inter_edge_w = (const float*)d_in[20];
    const int* edge_index = (const int*)d_in[21];
    const int* edge_type = (const int*)d_in[22];
    const int* inter_edge = (const int*)d_in[23];
    float* out = (float*)d_out;

    int NU = in_sizes[0] / D;
    int NI = in_sizes[1] / D;
    int NE = in_sizes[5] / KD;
    int E = in_sizes[22];
    int EI = in_sizes[20];
    const int* eh = edge_index;
    const int* et = edge_index + E;
    const int* users = inter_edge;
    const int* items = inter_edge + EI;

    float *userWq, *itemWk, *itemWv, *scores, *itemCoeff, *pref, *qc;
    float *omega, *alphaA, *etaA, *embA, *embB;
    int *degE, *rowE, *curE, *csrE, *degU, *rowU, *curU, *csrU;
    cudaGetSymbolAddress((void**)&userWq, g_userWq);
    cudaGetSymbolAddress((void**)&itemWk, g_itemWk);
    cudaGetSymbolAddress((void**)&itemWv, g_itemWv);
    cudaGetSymbolAddress((void**)&scores, g_scores);
    cudaGetSymbolAddress((void**)&itemCoeff, g_itemCoeff);
    cudaGetSymbolAddress((void**)&pref, g_pref);
    cudaGetSymbolAddress((void**)&qc, g_qc);
    cudaGetSymbolAddress((void**)&omega, g_omega);
    cudaGetSymbolAddress((void**)&alphaA, g_alphaA);
    cudaGetSymbolAddress((void**)&etaA, g_etaA);
    cudaGetSymbolAddress((void**)&embA, g_embA);
    cudaGetSymbolAddress((void**)&embB, g_embB);
    cudaGetSymbolAddress((void**)&degE, g_degE);
    cudaGetSymbolAddress((void**)&rowE, g_rowE);
    cudaGetSymbolAddress((void**)&curE, g_curE);
    cudaGetSymbolAddress((void**)&csrE, g_csrE);
    cudaGetSymbolAddress((void**)&degU, g_degU);
    cudaGetSymbolAddress((void**)&rowU, g_rowU);
    cudaGetSymbolAddress((void**)&curU, g_curU);
    cudaGetSymbolAddress((void**)&csrU, g_csrU);

    // init output (base embeddings)
    {
        int tot = (NE + NU) * 16;
        out_init_kernel<<<(tot + 255) / 256, 256>>>((float4*)out, (const float4*)entity_emb,
                                                    (const float4*)user_emb, NE * 16, NU * 16);
    }
    zero_kernel<<<(NE + 255) / 256, 256>>>(degE, degU, itemCoeff, pref, NE, NU, NI);

    // ---- CSR builds ----
    hist_kernel<<<(E + 255) / 256, 256>>>(eh, degE, E);
    hist_kernel<<<(EI + 255) / 256, 256>>>(users, degU, EI);
    exscan_kernel<<<1, 1024>>>(degE, rowE, NE);
    exscan_kernel<<<1, 1024>>>(degU, rowU, NU);
    copy_int_kernel<<<(NE + 255) / 256, 256>>>(rowE, curE, NE);
    copy_int_kernel<<<(NU + 255) / 256, 256>>>(rowU, curU, NU);
    fill_kernel<<<(E + 255) / 256, 256>>>(eh, curE, csrE, E);
    fill_kernel<<<(EI + 255) / 256, 256>>>(users, curU, csrU, EI);

    // ---- attention preference miner ----
    gemm64_kernel<<<(NU + 15) / 16, 1024>>>(user_embed, Wq, userWq, NU);
    gemm64_kernel<<<(NI + 15) / 16, 1024>>>(item_embed, Wk, itemWk, NI);
    gemm64_kernel<<<(NI + 15) / 16, 1024>>>(item_embed, Wv, itemWv, NI);
    {
        long long th = (long long)EI * 32;
        score_kernel<<<(int)((th + 255) / 256), 256>>>(userWq, itemWk, users, items,
                                                       inter_edge_w, scores, EI);
    }
    {
        long long th = (long long)NU * 32;
        usoftmax_kernel<<<(int)((th + 255) / 256), 256>>>(scores, items, rowU, csrU,
                                                          itemCoeff, NU);
    }
    pref_kernel<<<256, 64>>>(itemCoeff, itemWv, pref, NI);
    qc_kernel<<<1, 64>>>(rt_W2, rt_b2, pref, qc);

    // ---- fused fact-semantic + router ----
    int smem_bytes = SMEM_OMEGA_FLOATS * 4;
    cudaFuncSetAttribute(omega_kernel, cudaFuncAttributeMaxDynamicSharedMemorySize, smem_bytes);
    omega_kernel<<<(E + 255) / 256, 256, smem_bytes>>>(
        ent_real, ent_imag, rel_real, rel_imag, eh, et, edge_type,
        fp_W1, fp_b1, fp_W2, fp_b2, rt_W1, rt_b1, qc, omega, E);

    alphaeta_kernel<<<(NE + 255) / 256, 256>>>(omega, rowE, csrE, alphaA, etaA, NE);

    // ---- 3-hop graph conv (CSR gather, fused normalize) ----
    const float* srcs[3] = {entity_emb, embA, embB};
    float* dsts[3] = {embA, embB, embA};
    const float* rhos[3] = {alphaA, alphaA, etaA};
    for (int hop = 0; hop < 3; hop++) {
        {
            long long th = (long long)NE * 32;
            ehop_kernel<<<(int)((th + 255) / 256), 256>>>(srcs[hop], relation_emb, et, edge_type,
                                                          rhos[hop], rowE, csrE, dsts[hop], out, NE);
        }
        {
            long long th = (long long)NU * 32;
            uhop_kernel<<<(int)((th + 255) / 256), 256>>>(srcs[hop], items, inter_edge_w,
                                                          rowU, csrU, out + (size_t)NE * D, NU);
        }
    }
}

// round 3
// speedup vs baseline: 1.8000x; 1.5234x over previous
#include <cuda_runtime.h>
#include <math.h>

#define D 64
#define KD 32
#define MAXU 50000
#define MAXI 30000
#define MAXENT 100000
#define MAXE 500000
#define MAXEI 1000000
#define MAXREL 10
#define GAMMA 0.2f

typedef unsigned long long u64;

// ---------------- scratch (device globals; no allocation) ----------------
__device__ float g_userWq[MAXU * D];
__device__ float g_itemWk[MAXI * D];
__device__ float g_itemWv[MAXI * D];
__device__ float g_scoresG[MAXEI];   // scores in CSR-U order
__device__ float g_itemCoeff[MAXI];
__device__ float g_pref[D];
__device__ float g_qc[D + 1];
__device__ float g_omegaG[MAXE];     // omega in CSR-E order
__device__ float g_alphaG[MAXE];     // alpha in CSR-E order
__device__ float g_etaG[MAXE];       // eta in CSR-E order
__device__ float g_embA[MAXENT * D];
__device__ float g_embB[MAXENT * D];
__device__ int g_degE[MAXENT];
__device__ int g_rowE[MAXENT + 1];
__device__ int g_curE[MAXENT];
__device__ int g_posE[MAXE];
__device__ int g_tpackE[MAXE];       // et | (r<<20), CSR-E order
__device__ int g_degU[MAXU];
__device__ int g_rowU[MAXU + 1];
__device__ int g_curU[MAXU];
__device__ int g_posU[MAXEI];
__device__ int g_itemG[MAXEI];       // item, CSR-U order
__device__ float g_wG[MAXEI];        // edge weight, CSR-U order
// precomputed per-entity tables
__device__ float g_Ah[MAXENT * D];   // [er|ei] @ W1[0:64]
__device__ float g_At[MAXENT * D];   // [er|ei] @ W1[128:192]
__device__ float g_P[MAXENT * D];    // [er|ei] @ rtW1
__device__ float g_Arel[MAXREL * D]; // [rr|ri] @ W1[64:128]
__device__ float g_Prel[MAXREL * D]; // [rr|ri] @ rtW1

// ---------------- helpers ----------------
__device__ __forceinline__ float n2n(float x) {
    if (x != x) return 0.f;
    if (x == INFINITY) return 1e4f;
    if (x == -INFINITY) return 1e-4f;
    return x;
}
__device__ __forceinline__ float sigm(float x) {
    return __fdividef(1.f, 1.f + __expf(-x));
}
__device__ __forceinline__ u64 pack2(float x, float y) {
    u64 r;
    asm("mov.b64 %0, {%1, %2};" : "=l"(r) : "f"(x), "f"(y));
    return r;
}
__device__ __forceinline__ u64 ffma2(u64 a, u64 b, u64 c) {
    u64 d;
    asm("fma.rn.f32x2 %0, %1, %2, %3;" : "=l"(d) : "l"(a), "l"(b), "l"(c));
    return d;
}

// ---------------- init / CSR build ----------------
__global__ void out_init_kernel(float4* out, const float4* ent, const float4* usr,
                                int ne16, int nu16) {
    int i = blockIdx.x * blockDim.x + threadIdx.x;
    if (i < ne16) out[i] = ent[i];
    else if (i < ne16 + nu16) out[i] = usr[i - ne16];
}

__global__ void zero_kernel(int* degE, int* degU, float* ic, float* pref,
                            int NE, int NU, int NI) {
    int i = blockIdx.x * blockDim.x + threadIdx.x;
    if (i < NE) degE[i] = 0;
    if (i < NU) degU[i] = 0;
    if (i < NI) ic[i] = 0.f;
    if (i < 64) pref[i] = 0.f;
}

__global__ void hist_kernel(const int* __restrict__ idx, int* deg, int n) {
    int i = blockIdx.x * blockDim.x + threadIdx.x;
    if (i < n) atomicAdd(&deg[idx[i]], 1);
}

// single-block exclusive scan
__global__ void exscan_kernel(const int* __restrict__ deg, int* row, int n) {
    __shared__ int sh_carry;
    __shared__ int wsum[32];
    int tid = threadIdx.x, lane = tid & 31, wid = tid >> 5;
    if (tid == 0) sh_carry = 0;
    __syncthreads();
    for (int base = 0; base < n; base += blockDim.x) {
        int i = base + tid;
        int v = (i < n) ? deg[i] : 0;
        int s = v;
#pragma unroll
        for (int o = 1; o < 32; o <<= 1) {
            int t = __shfl_up_sync(0xffffffffu, s, o);
            if (lane >= o) s += t;
        }
        if (lane == 31) wsum[wid] = s;
        __syncthreads();
        if (wid == 0) {
            int ws = wsum[lane];
#pragma unroll
            for (int o = 1; o < 32; o <<= 1) {
                int t = __shfl_up_sync(0xffffffffu, ws, o);
                if (lane >= o) ws += t;
            }
            wsum[lane] = ws;
        }
        __syncthreads();
        int woff = (wid == 0) ? 0 : wsum[wid - 1];
        int excl = sh_carry + woff + s - v;
        if (i < n) row[i] = excl;
        int blocktot = wsum[(blockDim.x >> 5) - 1];
        __syncthreads();
        if (tid == 0) sh_carry += blocktot;
        __syncthreads();
    }
    if (threadIdx.x == 0) row[n] = sh_carry;
}

__global__ void copy_int_kernel(const int* __restrict__ a, int* b, int n) {
    int i = blockIdx.x * blockDim.x + threadIdx.x;
    if (i < n) b[i] = a[i];
}

__global__ void fillE_kernel(const int* __restrict__ eh, const int* __restrict__ et,
                             const int* __restrict__ etype, int* cur, int* pos,
                             int* tpack, int n) {
    int e = blockIdx.x * blockDim.x + threadIdx.x;
    if (e < n) {
        int p = atomicAdd(&cur[eh[e]], 1);
        pos[e] = p;
        tpack[p] = et[e] | ((etype[e] - 1) << 20);
    }
}

__global__ void fillU_kernel(const int* __restrict__ users, const int* __restrict__ items,
                             const float* __restrict__ w, int* cur, int* pos,
                             int* itemG, float* wG, int n) {
    int e = blockIdx.x * blockDim.x + threadIdx.x;
    if (e < n) {
        int p = atomicAdd(&cur[users[e]], 1);
        pos[e] = p;
        itemG[p] = items[e];
        wG[p] = w[e];
    }
}

// ---------------- small GEMM: Y[n,64] = X[n,64] @ W[64,64] ----------------
__global__ void gemm64_kernel(const float* __restrict__ X, const float* __restrict__ W,
                              float* __restrict__ Y, int nrows) {
    __shared__ float sW[64 * 64];
    __shared__ float sX[16 * 64];
    int tid = threadIdx.x;
    for (int i = tid; i < 4096; i += 1024) sW[i] = W[i];
    int r = tid >> 6, j = tid & 63;
    int row = blockIdx.x * 16 + r;
    if (row < nrows) sX[r * 64 + j] = X[row * 64 + j];
    __syncthreads();
    if (row < nrows) {
        float acc = 0.f;
#pragma unroll
        for (int k = 0; k < 64; k++) acc += sX[r * 64 + k] * sW[k * 64 + j];
        Y[row * 64 + j] = acc;
    }
}

// ---------------- entity precompute: Ah, At, P (3 tables, packed f32x2) -----
__global__ void entpre_kernel(const float* __restrict__ ent_real,
                              const float* __restrict__ ent_imag,
                              const float* __restrict__ fpW1,
                              const float* __restrict__ rtW1,
                              float* __restrict__ Ah, float* __restrict__ At,
                              float* __restrict__ P, int NE) {
    __shared__ float sWa[64 * 64];  // W1 rows 0:64
    __shared__ float sWb[64 * 64];  // W1 rows 128:192
    __shared__ float sWp[64 * 64];  // rtW1
    __shared__ float sX[32 * 64];
    int tid = threadIdx.x;  // 1024
    for (int i = tid; i < 4096; i += 1024) {
        sWa[i] = fpW1[i];
        sWb[i] = fpW1[128 * 64 + i];
        sWp[i] = rtW1[i];
    }
    int rowBase = blockIdx.x * 32;
    // load 32 input rows: [er(32) | ei(32)]
    for (int i = tid; i < 32 * 64; i += 1024) {
        int rl = i >> 6, k = i & 63;
        int n = rowBase + rl;
        float v = 0.f;
        if (n < NE) v = (k < 32) ? ent_real[n * KD + k] : ent_imag[n * KD + (k - 32)];
        sX[i] = v;
    }
    __syncthreads();
    int rl = tid >> 5, jp = tid & 31;  // row-local, col-pair
    int n = rowBase + rl;
    if (n >= NE) return;
    u64 a0 = 0, a1 = 0, a2 = 0;
    const u64* wa = (const u64*)sWa;
    const u64* wb = (const u64*)sWb;
    const u64* wp = (const u64*)sWp;
#pragma unroll 8
    for (int k = 0; k < 64; k++) {
        float xv = sX[rl * 64 + k];
        u64 xx = pack2(xv, xv);
        a0 = ffma2(xx, wa[k * 32 + jp], a0);
        a1 = ffma2(xx, wb[k * 32 + jp], a1);
        a2 = ffma2(xx, wp[k * 32 + jp], a2);
    }
    ((u64*)Ah)[n * 32 + jp] = a0;
    ((u64*)At)[n * 32 + jp] = a1;
    ((u64*)P)[n * 32 + jp] = a2;
}

// ---------------- relation precompute (tiny) ----------------
__global__ void relpre_kernel(const float* __restrict__ rel_real,
                              const float* __restrict__ rel_imag,
                              const float* __restrict__ fpW1,
                              const float* __restrict__ rtW1,
                              float* __restrict__ Arel, float* __restrict__ Prel, int NR) {
    int tid = threadIdx.x;
    int r = tid >> 6, j = tid & 63;
    if (r >= NR) return;
    float a = 0.f, p = 0.f;
    for (int k = 0; k < 64; k++) {
        float xv = (k < 32) ? rel_real[r * KD + k] : rel_imag[r * KD + (k - 32)];
        a += xv * fpW1[(64 + k) * 64 + j];
        p += xv * rtW1[k * 64 + j];
    }
    Arel[r * 64 + j] = a;
    Prel[r * 64 + j] = p;
}

// ---------------- miner ----------------
__global__ void score_kernel(const float* __restrict__ uq, const float* __restrict__ ik,
                             const int* __restrict__ users, const int* __restrict__ items,
                             const float* __restrict__ w, const int* __restrict__ posU,
                             float* __restrict__ scoresG, int EI) {
    int g = blockIdx.x * blockDim.x + threadIdx.x;
    int e = g >> 5, lane = g & 31;
    if (e >= EI) return;
    int u = users[e], it = items[e];
    float2 q = ((const float2*)uq)[u * 32 + lane];
    float2 k = ((const float2*)ik)[it * 32 + lane];
    float p = q.x * k.x + q.y * k.y;
#pragma unroll
    for (int o = 16; o; o >>= 1) p += __shfl_xor_sync(0xffffffffu, p, o);
    if (lane == 0) scoresG[posU[e]] = p * 0.125f * w[e];
}

// warp per user: softmax over its CSR range, scatter coeff to items
__global__ void usoftmax_kernel(const float* __restrict__ scoresG, const int* __restrict__ itemG,
                                const int* __restrict__ rowU, float* itemCoeff, int NU) {
    int g = blockIdx.x * blockDim.x + threadIdx.x;
    int u = g >> 5, lane = g & 31;
    if (u >= NU) return;
    int s = rowU[u], e = rowU[u + 1];
    int deg = e - s;
    if (deg == 0) return;
    float m = -INFINITY;
    for (int i = s + lane; i < e; i += 32) m = fmaxf(m, scoresG[i]);
#pragma unroll
    for (int o = 16; o; o >>= 1) m = fmaxf(m, __shfl_xor_sync(0xffffffffu, m, o));
    float den = 0.f;
    for (int i = s + lane; i < e; i += 32) den += __expf(scoresG[i] - m);
#pragma unroll
    for (int o = 16; o; o >>= 1) den += __shfl_xor_sync(0xffffffffu, den, o);
    float invc = __fdividef(1.f, den * fmaxf((float)deg, 1.f));
    for (int i = s + lane; i < e; i += 32)
        atomicAdd(&itemCoeff[itemG[i]], __expf(scoresG[i] - m) * invc);
}

__global__ void pref_kernel(const float* __restrict__ itemCoeff,
                            const float* __restrict__ itemWv, float* pref, int NI) {
    int j = threadIdx.x;  // 64
    float acc = 0.f;
    for (int i = blockIdx.x; i < NI; i += gridDim.x)
        acc += itemCoeff[i] * itemWv[i * 64 + j];
    atomicAdd(&pref[j], acc);
}

__global__ void qc_kernel(const float* __restrict__ rtW2, const float* __restrict__ rtb2,
                          const float* __restrict__ pref, float* qc) {
    __shared__ float sp[64];
    __shared__ float red[64];
    int j = threadIdx.x;
    sp[j] = pref[j];
    __syncthreads();
    float q = 0.f;
#pragma unroll
    for (int k = 0; k < 64; k++) q += rtW2[j * 64 + k] * sp[k];
    qc[j] = q * 0.125f;
    red[j] = rtb2[j] * sp[j];
    __syncthreads();
    if (j == 0) {
        float c = 0.f;
        for (int k = 0; k < 64; k++) c += red[k];
        qc[64] = c * 0.125f;
    }
}

// ---------------- omega via precomputed tables (thread per edge) ----------------
__global__ void omega_kernel(const float* __restrict__ Ah, const float* __restrict__ At,
                             const float* __restrict__ P,
                             const float* __restrict__ Arel, const float* __restrict__ Prel,
                             const int* __restrict__ eh, const int* __restrict__ et,
                             const int* __restrict__ etype,
                             const float* __restrict__ fpb1, const float* __restrict__ fpW2,
                             const float* __restrict__ fpb2, const float* __restrict__ rtb1,
                             const float* __restrict__ qc, const int* __restrict__ posE,
                             float* __restrict__ omegaG, int NR, int E) {
    __shared__ float sAr[MAXREL * 64];
    __shared__ float sPr[MAXREL * 64];
    __shared__ float sb1[64], srb1[64], sq[64], sW2[192];
    __shared__ float sb2[3];
    __shared__ float sc0;
    int tid = threadIdx.x;
    for (int i = tid; i < NR * 64; i += blockDim.x) {
        sAr[i] = Arel[i];
        sPr[i] = Prel[i];
    }
    for (int i = tid; i < 64; i += blockDim.x) {
        sb1[i] = fpb1[i];
        srb1[i] = rtb1[i];
        sq[i] = qc[i];
    }
    for (int i = tid; i < 192; i += blockDim.x) sW2[i] = fpW2[i];
    if (tid < 3) sb2[tid] = fpb2[tid];
    if (tid == 0) sc0 = qc[64];
    __syncthreads();

    int e = blockIdx.x * blockDim.x + tid;
    if (e >= E) return;
    int h = eh[e], t = et[e], r = etype[e] - 1;

    const float4* ah = (const float4*)(Ah + (size_t)h * 64);
    const float4* at = (const float4*)(At + (size_t)t * 64);
    const float4* ar = (const float4*)(sAr + r * 64);
    const float4* b14 = (const float4*)sb1;

    float z0 = sb2[0], z1 = sb2[1], z2 = sb2[2];
#pragma unroll
    for (int jq = 0; jq < 16; jq++) {
        float4 a = ah[jq], b = ar[jq], c = at[jq], bb = b14[jq];
        float s0 = sigm(a.x + b.x + c.x + bb.x);
        float s1 = sigm(a.y + b.y + c.y + bb.y);
        float s2 = sigm(a.z + b.z + c.z + bb.z);
        float s3 = sigm(a.w + b.w + c.w + bb.w);
        int j = jq * 4;
        z0 += s0 * sW2[j * 3] + s1 * sW2[(j + 1) * 3] + s2 * sW2[(j + 2) * 3] + s3 * sW2[(j + 3) * 3];
        z1 += s0 * sW2[j * 3 + 1] + s1 * sW2[(j + 1) * 3 + 1] + s2 * sW2[(j + 2) * 3 + 1] + s3 * sW2[(j + 3) * 3 + 1];
        z2 += s0 * sW2[j * 3 + 2] + s1 * sW2[(j + 1) * 3 + 2] + s2 * sW2[(j + 2) * 3 + 2] + s3 * sW2[(j + 3) * 3 + 2];
    }
    float mx = fmaxf(z0, fmaxf(z1, z2));
    float e0 = __expf(z0 - mx), e1 = __expf(z1 - mx), e2 = __expf(z2 - mx);
    float inv = __fdividef(1.f, e0 + e1 + e2);
    float w0 = e0 * inv, w1 = e1 * inv, w2 = e2 * inv;

    const float4* ph = (const float4*)(P + (size_t)h * 64);
    const float4* pt = (const float4*)(P + (size_t)t * 64);
    const float4* pr = (const float4*)(sPr + r * 64);
    const float4* rb4 = (const float4*)srb1;
    const float4* q4 = (const float4*)sq;

    float om = sc0;
#pragma unroll
    for (int jq = 0; jq < 16; jq++) {
        float4 a = ph[jq], b = pr[jq], c = pt[jq], bb = rb4[jq], qv = q4[jq];
        om += qv.x * sigm(w0 * a.x + w1 * b.x + w2 * c.x + bb.x);
        om += qv.y * sigm(w0 * a.y + w1 * b.y + w2 * c.y + bb.y);
        om += qv.z * sigm(w0 * a.z + w1 * b.z + w2 * c.z + bb.z);
        om += qv.w * sigm(w0 * a.w + w1 * b.w + w2 * c.w + bb.w);
    }
    omegaG[posE[e]] = om;
}

// ---------------- alpha / eta in CSR order (thread per head) ----------------
__global__ void alphaeta_kernel(const float* __restrict__ omegaG, const int* __restrict__ rowE,
                                float* __restrict__ alphaG, float* __restrict__ etaG, int NE) {
    int h = blockIdx.x * blockDim.x + threadIdx.x;
    if (h >= NE) return;
    int s = rowE[h], e = rowE[h + 1];
    if (s == e) return;
    float so = 0.f;
    for (int i = s; i < e; i++) so += omegaG[i];
    float d1 = so + 1e-8f;
    float se = 0.f;
    for (int i = s; i < e; i++) {
        float a = omegaG[i] / d1;
        se += (a > GAMMA) ? a : 0.f;
    }
    float d2 = se + 1e-8f;
    for (int i = s; i < e; i++) {
        float a = omegaG[i] / d1;
        alphaG[i] = a;
        float e0 = (a > GAMMA) ? a : 0.f;
        etaG[i] = e0 / d2;
    }
}

// ---------------- merged hop kernel: entity rows then user rows ----------------
__global__ void hop_kernel(const float* __restrict__ src, const float* __restrict__ relemb,
                           const int* __restrict__ tpackE, const float* __restrict__ rho,
                           const int* __restrict__ rowE,
                           const int* __restrict__ itemG, const float* __restrict__ wG,
                           const int* __restrict__ rowU,
                           float* __restrict__ dst, float* __restrict__ outE,
                           float* __restrict__ outU, int NE, int NU, int NR) {
    __shared__ float sRel[MAXREL * 64];
    int tid = threadIdx.x;
    for (int i = tid; i < NR * 64; i += blockDim.x) sRel[i] = relemb[i];
    __syncthreads();

    int g = blockIdx.x * blockDim.x + tid;
    int row = g >> 5, lane = g & 31;
    if (row >= NE + NU) return;
    const float2* src2 = (const float2*)src;

    if (row < NE) {
        int h = row;
        int s = rowE[h], e1 = rowE[h + 1];
        float2 acc = make_float2(0.f, 0.f);
        int i = s;
        for (; i + 4 <= e1; i += 4) {
            int tp0 = tpackE[i], tp1 = tpackE[i + 1], tp2 = tpackE[i + 2], tp3 = tpackE[i + 3];
            float r0 = rho[i], r1 = rho[i + 1], r2 = rho[i + 2], r3 = rho[i + 3];
            float2 x0 = src2[(size_t)(tp0 & 0xFFFFF) * 32 + lane];
            float2 x1 = src2[(size_t)(tp1 & 0xFFFFF) * 32 + lane];
            float2 x2 = src2[(size_t)(tp2 & 0xFFFFF) * 32 + lane];
            float2 x3 = src2[(size_t)(tp3 & 0xFFFFF) * 32 + lane];
            float2 w0 = ((const float2*)sRel)[(tp0 >> 20) * 32 + lane];
            float2 w1 = ((const float2*)sRel)[(tp1 >> 20) * 32 + lane];
            float2 w2 = ((const float2*)sRel)[(tp2 >> 20) * 32 + lane];
            float2 w3 = ((const float2*)sRel)[(tp3 >> 20) * 32 + lane];
            acc.x += r0 * x0.x * w0.x + r1 * x1.x * w1.x + r2 * x2.x * w2.x + r3 * x3.x * w3.x;
            acc.y += r0 * x0.y * w0.y + r1 * x1.y * w1.y + r2 * x2.y * w2.y + r3 * x3.y * w3.y;
        }
        for (; i < e1; i++) {
            int tp = tpackE[i];
            float rv = rho[i];
            float2 x = src2[(size_t)(tp & 0xFFFFF) * 32 + lane];
            float2 w = ((const float2*)sRel)[(tp >> 20) * 32 + lane];
            acc.x += rv * x.x * w.x;
            acc.y += rv * x.y * w.y;
        }
        float c = fmaxf((float)(e1 - s), 1.f);
        acc.x /= c;
        acc.y /= c;
        float ss = acc.x * acc.x + acc.y * acc.y;
#pragma unroll
        for (int o = 16; o; o >>= 1) ss += __shfl_xor_sync(0xffffffffu, ss, o);
        float inv = 1.f / fmaxf(sqrtf(ss), 1e-8f);
        float a = n2n(acc.x * inv), b = n2n(acc.y * inv);
        ((float2*)dst)[(size_t)h * 32 + lane] = make_float2(a, b);
        float2 o2 = ((float2*)outE)[(size_t)h * 32 + lane];
        o2.x += a;
        o2.y += b;
        ((float2*)outE)[(size_t)h * 32 + lane] = o2;
    } else {
        int u = row - NE;
        int s = rowU[u], e1 = rowU[u + 1];
        float2 acc = make_float2(0.f, 0.f);
        int i = s;
        for (; i + 4 <= e1; i += 4) {
            int it0 = itemG[i], it1 = itemG[i + 1], it2 = itemG[i + 2], it3 = itemG[i + 3];
            float w0 = wG[i], w1 = wG[i + 1], w2 = wG[i + 2], w3 = wG[i + 3];
            float2 x0 = src2[(size_t)it0 * 32 + lane];
            float2 x1 = src2[(size_t)it1 * 32 + lane];
            float2 x2 = src2[(size_t)it2 * 32 + lane];
            float2 x3 = src2[(size_t)it3 * 32 + lane];
            acc.x += w0 * x0.x + w1 * x1.x + w2 * x2.x + w3 * x3.x;
            acc.y += w0 * x0.y + w1 * x1.y + w2 * x2.y + w3 * x3.y;
        }
        for (; i < e1; i++) {
            int it = itemG[i];
            float wv = wG[i];
            float2 x = src2[(size_t)it * 32 + lane];
            acc.x += wv * x.x;
            acc.y += wv * x.y;
        }
        float ss = acc.x * acc.x + acc.y * acc.y;
#pragma unroll
        for (int o = 16; o; o >>= 1) ss += __shfl_xor_sync(0xffffffffu, ss, o);
        float inv = 1.f / fmaxf(sqrtf(ss), 1e-8f);
        float a = n2n(acc.x * inv), b = n2n(acc.y * inv);
        float2 o2 = ((float2*)outU)[(size_t)u * 32 + lane];
        o2.x += a;
        o2.y += b;
        ((float2*)outU)[(size_t)u * 32 + lane] = o2;
    }
}

// ---------------- launch ----------------
extern "C" void kernel_launch(void* const* d_in, const int* in_sizes, int n_in,
                              void* d_out, int out_size) {
    const float* user_embed = (const float*)d_in[0];
    const float* item_embed = (const float*)d_in[1];
    const float* Wq = (const float*)d_in[2];
    const float* Wk = (const float*)d_in[3];
    const float* Wv = (const float*)d_in[4];
    const float* ent_real = (const float*)d_in[5];
    const float* ent_imag = (const float*)d_in[6];
    const float* rel_real = (const float*)d_in[7];
    const float* rel_imag = (const float*)d_in[8];
    const float* fp_W1 = (const float*)d_in[9];
    const float* fp_b1 = (const float*)d_in[10];
    const float* fp_W2 = (const float*)d_in[11];
    const float* fp_b2 = (const float*)d_in[12];
    const float* rt_W1 = (const float*)d_in[13];
    const float* rt_b1 = (const float*)d_in[14];
    const float* rt_W2 = (const float*)d_in[15];
    const float* rt_b2 = (const float*)d_in[16];
    const float* relation_emb = (const float*)d_in[17];
    const float* user_emb = (const float*)d_in[18];
    const float* entity_emb = (const float*)d_in[19];
    const float* inter_edge_w = (const float*)d_in[20];
    const int* edge_index = (const int*)d_in[21];
    const int* edge_type = (const int*)d_in[22];
    const int* inter_edge = (const int*)d_in[23];
    float* out = (float*)d_out;

    int NU = in_sizes[0] / D;
    int NI = in_sizes[1] / D;
    int NE = in_sizes[5] / KD;
    int NR = in_sizes[7] / KD;
    int E = in_sizes[22];
    int EI = in_sizes[20];
    const int* eh = edge_index;
    const int* et = edge_index + E;
    const int* users = inter_edge;
    const int* items = inter_edge + EI;

    float *userWq, *itemWk, *itemWv, *scoresG, *itemCoeff, *pref, *qc;
    float *omegaG, *alphaG, *etaG, *embA, *embB, *wG;
    float *Ah, *At, *P, *Arel, *Prel;
    int *degE, *rowE, *curE, *posE, *tpackE, *degU, *rowU, *curU, *posU, *itemG;
    cudaGetSymbolAddress((void**)&userWq, g_userWq);
    cudaGetSymbolAddress((void**)&itemWk, g_itemWk);
    cudaGetSymbolAddress((void**)&itemWv, g_itemWv);
    cudaGetSymbolAddress((void**)&scoresG, g_scoresG);
    cudaGetSymbolAddress((void**)&itemCoeff, g_itemCoeff);
    cudaGetSymbolAddress((void**)&pref, g_pref);
    cudaGetSymbolAddress((void**)&qc, g_qc);
    cudaGetSymbolAddress((void**)&omegaG, g_omegaG);
    cudaGetSymbolAddress((void**)&alphaG, g_alphaG);
    cudaGetSymbolAddress((void**)&etaG, g_etaG);
    cudaGetSymbolAddress((void**)&embA, g_embA);
    cudaGetSymbolAddress((void**)&embB, g_embB);
    cudaGetSymbolAddress((void**)&degE, g_degE);
    cudaGetSymbolAddress((void**)&rowE, g_rowE);
    cudaGetSymbolAddress((void**)&curE, g_curE);
    cudaGetSymbolAddress((void**)&posE, g_posE);
    cudaGetSymbolAddress((void**)&tpackE, g_tpackE);
    cudaGetSymbolAddress((void**)&degU, g_degU);
    cudaGetSymbolAddress((void**)&rowU, g_rowU);
    cudaGetSymbolAddress((void**)&curU, g_curU);
    cudaGetSymbolAddress((void**)&posU, g_posU);
    cudaGetSymbolAddress((void**)&itemG, g_itemG);
    cudaGetSymbolAddress((void**)&wG, g_wG);
    cudaGetSymbolAddress((void**)&Ah, g_Ah);
    cudaGetSymbolAddress((void**)&At, g_At);
    cudaGetSymbolAddress((void**)&P, g_P);
    cudaGetSymbolAddress((void**)&Arel, g_Arel);
    cudaGetSymbolAddress((void**)&Prel, g_Prel);

    // init output (base embeddings)
    {
        int tot = (NE + NU) * 16;
        out_init_kernel<<<(tot + 255) / 256, 256>>>((float4*)out, (const float4*)entity_emb,
                                                    (const float4*)user_emb, NE * 16, NU * 16);
    }
    zero_kernel<<<(NE + 255) / 256, 256>>>(degE, degU, itemCoeff, pref, NE, NU, NI);

    // ---- CSR builds ----
    hist_kernel<<<(E + 255) / 256, 256>>>(eh, degE, E);
    hist_kernel<<<(EI + 255) / 256, 256>>>(users, degU, EI);
    exscan_kernel<<<1, 1024>>>(degE, rowE, NE);
    exscan_kernel<<<1, 1024>>>(degU, rowU, NU);
    copy_int_kernel<<<(NE + 255) / 256, 256>>>(rowE, curE, NE);
    copy_int_kernel<<<(NU + 255) / 256, 256>>>(rowU, curU, NU);
    fillE_kernel<<<(E + 255) / 256, 256>>>(eh, et, edge_type, curE, posE, tpackE, E);
    fillU_kernel<<<(EI + 255) / 256, 256>>>(users, items, inter_edge_w, curU, posU, itemG, wG, EI);

    // ---- precompute entity/relation tables ----
    entpre_kernel<<<(NE + 31) / 32, 1024>>>(ent_real, ent_imag, fp_W1, rt_W1, Ah, At, P, NE);
    relpre_kernel<<<1, NR * 64>>>(rel_real, rel_imag, fp_W1, rt_W1, Arel, Prel, NR);

    // ---- attention preference miner ----
    gemm64_kernel<<<(NU + 15) / 16, 1024>>>(user_embed, Wq, userWq, NU);
    gemm64_kernel<<<(NI + 15) / 16, 1024>>>(item_embed, Wk, itemWk, NI);
    gemm64_kernel<<<(NI + 15) / 16, 1024>>>(item_embed, Wv, itemWv, NI);
    {
        long long th = (long long)EI * 32;
        score_kernel<<<(int)((th + 255) / 256), 256>>>(userWq, itemWk, users, items,
                                                       inter_edge_w, posU, scoresG, EI);
    }
    {
        long long th = (long long)NU * 32;
        usoftmax_kernel<<<(int)((th + 255) / 256), 256>>>(scoresG, itemG, rowU, itemCoeff, NU);
    }
    pref_kernel<<<256, 64>>>(itemCoeff, itemWv, pref, NI);
    qc_kernel<<<1, 64>>>(rt_W2, rt_b2, pref, qc);

    // ---- omega from tables ----
    omega_kernel<<<(E + 255) / 256, 256>>>(Ah, At, P, Arel, Prel, eh, et, edge_type,
                                           fp_b1, fp_W2, fp_b2, rt_b1, qc, posE,
                                           omegaG, NR, E);

    alphaeta_kernel<<<(NE + 255) / 256, 256>>>(omegaG, rowE, alphaG, etaG, NE);

    // ---- 3-hop graph conv (merged entity+user gather) ----
    const float* srcs[3] = {entity_emb, embA, embB};
    float* dsts[3] = {embA, embB, embA};
    const float* rhos[3] = {alphaG, alphaG, etaG};
    for (int hop = 0; hop < 3; hop++) {
        long long th = (long long)(NE + NU) * 32;
        hop_kernel<<<(int)((th + 255) / 256), 256>>>(
            srcs[hop], relation_emb, tpackE, rhos[hop], rowE, itemG, wG, rowU,
            dsts[hop], out, out + (size_t)NE * D, NE, NU, NR);
    }
}

// round 4
// speedup vs baseline: 2.4352x; 1.3529x over previous
#include <cuda_runtime.h>
#include <math.h>

#define D 64
#define KD 32
#define MAXU 50000
#define MAXI 30000
#define MAXENT 100000
#define MAXE 500000
#define MAXEI 1000000
#define MAXREL 10
#define GAMMA 0.2f

typedef unsigned long long u64;

// ---------------- scratch (device globals; no allocation) ----------------
__device__ float g_userWq[MAXU * D];
__device__ float g_itemWk[MAXI * D];
__device__ float g_itemWv[MAXI * D];
__device__ float g_scoresG[MAXEI];   // scores in CSR-U order
__device__ float g_itemCoeff[MAXI];
__device__ float g_pref[D];
__device__ float g_qc[D + 1];
__device__ float g_omegaG[MAXE];     // omega in CSR-E order
__device__ float g_alphaG[MAXE];
__device__ float g_etaG[MAXE];
__device__ float g_embA[MAXENT * D];
__device__ float g_embB[MAXENT * D];
__device__ int g_degE[MAXENT];
__device__ int g_rowE[MAXENT + 1];
__device__ int g_curE[MAXENT];
__device__ int g_posE[MAXE];
__device__ int g_tpackE[MAXE];       // et | (r<<20), CSR-E order
__device__ int g_degU[MAXU];
__device__ int g_rowU[MAXU + 1];
__device__ int g_curU[MAXU];
__device__ int g_posU[MAXEI];
__device__ int g_itemG[MAXEI];       // item, CSR-U order
__device__ float g_wG[MAXEI];        // edge weight, CSR-U order
// precomputed per-entity tables
__device__ float g_Ah[MAXENT * D];   // [er|ei] @ W1[0:64]
__device__ float g_At[MAXENT * D];   // [er|ei] @ W1[128:192]
__device__ float g_P[MAXENT * D];    // [er|ei] @ rtW1
__device__ float g_Arel[MAXREL * D];
__device__ float g_Prel[MAXREL * D];

// ---------------- helpers ----------------
__device__ __forceinline__ float n2n(float x) {
    if (x != x) return 0.f;
    if (x == INFINITY) return 1e4f;
    if (x == -INFINITY) return 1e-4f;
    return x;
}
__device__ __forceinline__ float sigm(float x) {
    return __fdividef(1.f, 1.f + __expf(-x));
}
__device__ __forceinline__ u64 pack2(float x, float y) {
    u64 r;
    asm("mov.b64 %0, {%1, %2};" : "=l"(r) : "f"(x), "f"(y));
    return r;
}
__device__ __forceinline__ u64 ffma2(u64 a, u64 b, u64 c) {
    u64 d;
    asm("fma.rn.f32x2 %0, %1, %2, %3;" : "=l"(d) : "l"(a), "l"(b), "l"(c));
    return d;
}
// reduce over 16-lane subwarp
__device__ __forceinline__ float red16(float v) {
#pragma unroll
    for (int o = 8; o; o >>= 1) v += __shfl_xor_sync(0xffffffffu, v, o);
    return v;
}

// ---------------- init / CSR build ----------------
__global__ void out_init_kernel(float4* out, const float4* ent, const float4* usr,
                                int ne16, int nu16) {
    int i = blockIdx.x * blockDim.x + threadIdx.x;
    if (i < ne16) out[i] = ent[i];
    else if (i < ne16 + nu16) out[i] = usr[i - ne16];
}

__global__ void zero_kernel(int* degE, int* degU, float* ic, float* pref,
                            int NE, int NU, int NI) {
    int i = blockIdx.x * blockDim.x + threadIdx.x;
    if (i < NE) degE[i] = 0;
    if (i < NU) degU[i] = 0;
    if (i < NI) ic[i] = 0.f;
    if (i < 64) pref[i] = 0.f;
}

__global__ void hist2_kernel(const int* __restrict__ eh, const int* __restrict__ users,
                             int* degE, int* degU, int E, int EI) {
    int i = blockIdx.x * blockDim.x + threadIdx.x;
    if (i < E) atomicAdd(&degE[eh[i]], 1);
    else if (i < E + EI) atomicAdd(&degU[users[i - E]], 1);
}

// exclusive scan; block 0 -> (degA,rowA,nA), block 1 -> (degB,rowB,nB)
__global__ void exscan2_kernel(const int* __restrict__ degA, int* rowA, int nA,
                               const int* __restrict__ degB, int* rowB, int nB) {
    const int* deg = (blockIdx.x == 0) ? degA : degB;
    int* row = (blockIdx.x == 0) ? rowA : rowB;
    int n = (blockIdx.x == 0) ? nA : nB;
    __shared__ int sh_carry;
    __shared__ int wsum[32];
    int tid = threadIdx.x, lane = tid & 31, wid = tid >> 5;
    if (tid == 0) sh_carry = 0;
    __syncthreads();
    for (int base = 0; base < n; base += blockDim.x) {
        int i = base + tid;
        int v = (i < n) ? deg[i] : 0;
        int s = v;
#pragma unroll
        for (int o = 1; o < 32; o <<= 1) {
            int t = __shfl_up_sync(0xffffffffu, s, o);
            if (lane >= o) s += t;
        }
        if (lane == 31) wsum[wid] = s;
        __syncthreads();
        if (wid == 0) {
            int ws = wsum[lane];
#pragma unroll
            for (int o = 1; o < 32; o <<= 1) {
                int t = __shfl_up_sync(0xffffffffu, ws, o);
                if (lane >= o) ws += t;
            }
            wsum[lane] = ws;
        }
        __syncthreads();
        int woff = (wid == 0) ? 0 : wsum[wid - 1];
        int excl = sh_carry + woff + s - v;
        if (i < n) row[i] = excl;
        int blocktot = wsum[(blockDim.x >> 5) - 1];
        __syncthreads();
        if (tid == 0) sh_carry += blocktot;
        __syncthreads();
    }
    if (threadIdx.x == 0) row[n] = sh_carry;
}

__global__ void copy2_kernel(const int* __restrict__ rowE, int* curE, int NE,
                             const int* __restrict__ rowU, int* curU, int NU) {
    int i = blockIdx.x * blockDim.x + threadIdx.x;
    if (i < NE) curE[i] = rowE[i];
    if (i < NU) curU[i] = rowU[i];
}

__global__ void fill2_kernel(const int* __restrict__ eh, const int* __restrict__ et,
                             const int* __restrict__ etype, int* curE, int* posE, int* tpackE,
                             int E,
                             const int* __restrict__ users, const int* __restrict__ items,
                             const float* __restrict__ w, int* curU, int* posU,
                             int* itemG, float* wG, int EI) {
    int i = blockIdx.x * blockDim.x + threadIdx.x;
    if (i < E) {
        int p = atomicAdd(&curE[eh[i]], 1);
        posE[i] = p;
        tpackE[p] = et[i] | ((etype[i] - 1) << 20);
    } else if (i < E + EI) {
        int e = i - E;
        int p = atomicAdd(&curU[users[e]], 1);
        posU[e] = p;
        itemG[p] = items[e];
        wG[p] = w[e];
    }
}

// ---------------- entity precompute: Ah, At, P ----------------
__global__ void entpre_kernel(const float* __restrict__ ent_real,
                              const float* __restrict__ ent_imag,
                              const float* __restrict__ fpW1,
                              const float* __restrict__ rtW1,
                              float* __restrict__ Ah, float* __restrict__ At,
                              float* __restrict__ P, int NE) {
    __shared__ float sWa[64 * 64];
    __shared__ float sWb[64 * 64];
    __shared__ float sWp[64 * 64];
    __shared__ float sX[32 * 64];
    int tid = threadIdx.x;  // 1024
    for (int i = tid; i < 4096; i += 1024) {
        sWa[i] = fpW1[i];
        sWb[i] = fpW1[128 * 64 + i];
        sWp[i] = rtW1[i];
    }
    int rowBase = blockIdx.x * 32;
    for (int i = tid; i < 32 * 64; i += 1024) {
        int rl = i >> 6, k = i & 63;
        int n = rowBase + rl;
        float v = 0.f;
        if (n < NE) v = (k < 32) ? ent_real[n * KD + k] : ent_imag[n * KD + (k - 32)];
        sX[i] = v;
    }
    __syncthreads();
    int rl = tid >> 5, jp = tid & 31;
    int n = rowBase + rl;
    if (n >= NE) return;
    u64 a0 = 0, a1 = 0, a2 = 0;
    const u64* wa = (const u64*)sWa;
    const u64* wb = (const u64*)sWb;
    const u64* wp = (const u64*)sWp;
#pragma unroll 8
    for (int k = 0; k < 64; k++) {
        float xv = sX[rl * 64 + k];
        u64 xx = pack2(xv, xv);
        a0 = ffma2(xx, wa[k * 32 + jp], a0);
        a1 = ffma2(xx, wb[k * 32 + jp], a1);
        a2 = ffma2(xx, wp[k * 32 + jp], a2);
    }
    ((u64*)Ah)[n * 32 + jp] = a0;
    ((u64*)At)[n * 32 + jp] = a1;
    ((u64*)P)[n * 32 + jp] = a2;
}

// ---------------- relation precompute ----------------
__global__ void relpre_kernel(const float* __restrict__ rel_real,
                              const float* __restrict__ rel_imag,
                              const float* __restrict__ fpW1,
                              const float* __restrict__ rtW1,
                              float* __restrict__ Arel, float* __restrict__ Prel, int NR) {
    int tid = threadIdx.x;
    int r = tid >> 6, j = tid & 63;
    if (r >= NR) return;
    float a = 0.f, p = 0.f;
    for (int k = 0; k < 64; k++) {
        float xv = (k < 32) ? rel_real[r * KD + k] : rel_imag[r * KD + (k - 32)];
        a += xv * fpW1[(64 + k) * 64 + j];
        p += xv * rtW1[k * 64 + j];
    }
    Arel[r * 64 + j] = a;
    Prel[r * 64 + j] = p;
}

// ---------------- small GEMM: Y[n,64] = X[n,64] @ W[64,64] ----------------
__global__ void gemm64_kernel(const float* __restrict__ X, const float* __restrict__ W,
                              float* __restrict__ Y, int nrows) {
    __shared__ float sW[64 * 64];
    __shared__ float sX[16 * 64];
    int tid = threadIdx.x;
    for (int i = tid; i < 4096; i += 1024) sW[i] = W[i];
    int r = tid >> 6, j = tid & 63;
    int row = blockIdx.x * 16 + r;
    if (row < nrows) sX[r * 64 + j] = X[row * 64 + j];
    __syncthreads();
    if (row < nrows) {
        float acc = 0.f;
#pragma unroll
        for (int k = 0; k < 64; k++) acc += sX[r * 64 + k] * sW[k * 64 + j];
        Y[row * 64 + j] = acc;
    }
}

// ---------------- miner: 16-lane subwarp per edge ----------------
__global__ void score_kernel(const float* __restrict__ uq, const float* __restrict__ ik,
                             const int* __restrict__ users, const int* __restrict__ items,
                             const float* __restrict__ w, const int* __restrict__ posU,
                             float* __restrict__ scoresG, int EI) {
    int g = blockIdx.x * blockDim.x + threadIdx.x;
    int e = g >> 4, lane = g & 15;
    if (e >= EI) return;
    int u = users[e], it = items[e];
    float4 q = ((const float4*)uq)[u * 16 + lane];
    float4 k = ((const float4*)ik)[it * 16 + lane];
    float p = q.x * k.x + q.y * k.y + q.z * k.z + q.w * k.w;
    p = red16(p);
    if (lane == 0) scoresG[posU[e]] = p * 0.125f * w[e];
}

// warp per user: softmax over its CSR range, scatter coeff to items
__global__ void usoftmax_kernel(const float* __restrict__ scoresG, const int* __restrict__ itemG,
                                const int* __restrict__ rowU, float* itemCoeff, int NU) {
    int g = blockIdx.x * blockDim.x + threadIdx.x;
    int u = g >> 5, lane = g & 31;
    if (u >= NU) return;
    int s = rowU[u], e = rowU[u + 1];
    int deg = e - s;
    if (deg == 0) return;
    float m = -INFINITY;
    for (int i = s + lane; i < e; i += 32) m = fmaxf(m, scoresG[i]);
#pragma unroll
    for (int o = 16; o; o >>= 1) m = fmaxf(m, __shfl_xor_sync(0xffffffffu, m, o));
    float den = 0.f;
    for (int i = s + lane; i < e; i += 32) den += __expf(scoresG[i] - m);
#pragma unroll
    for (int o = 16; o; o >>= 1) den += __shfl_xor_sync(0xffffffffu, den, o);
    float invc = __fdividef(1.f, den * fmaxf((float)deg, 1.f));
    for (int i = s + lane; i < e; i += 32)
        atomicAdd(&itemCoeff[itemG[i]], __expf(scoresG[i] - m) * invc);
}

__global__ void pref_kernel(const float* __restrict__ itemCoeff,
                            const float* __restrict__ itemWv, float* pref, int NI) {
    int j = threadIdx.x;  // 64
    float acc = 0.f;
    for (int i = blockIdx.x; i < NI; i += gridDim.x)
        acc += itemCoeff[i] * itemWv[i * 64 + j];
    atomicAdd(&pref[j], acc);
}

__global__ void qc_kernel(const float* __restrict__ rtW2, const float* __restrict__ rtb2,
                          const float* __restrict__ pref, float* qc) {
    __shared__ float sp[64];
    __shared__ float red[64];
    int j = threadIdx.x;
    sp[j] = pref[j];
    __syncthreads();
    float q = 0.f;
#pragma unroll
    for (int k = 0; k < 64; k++) q += rtW2[j * 64 + k] * sp[k];
    qc[j] = q * 0.125f;
    red[j] = rtb2[j] * sp[j];
    __syncthreads();
    if (j == 0) {
        float c = 0.f;
        for (int k = 0; k < 64; k++) c += red[k];
        qc[64] = c * 0.125f;
    }
}

// ---------------- omega: 16-lane subwarp per edge, coalesced rows ----------------
__global__ void omega_kernel(const float* __restrict__ Ah, const float* __restrict__ At,
                             const float* __restrict__ P,
                             const float* __restrict__ Arel, const float* __restrict__ Prel,
                             const int* __restrict__ eh, const int* __restrict__ et,
                             const int* __restrict__ etype,
                             const float* __restrict__ fpb1, const float* __restrict__ fpW2,
                             const float* __restrict__ fpb2, const float* __restrict__ rtb1,
                             const float* __restrict__ qc, const int* __restrict__ posE,
                             float* __restrict__ omegaG, int NR, int E) {
    __shared__ float sAr[MAXREL * 64];
    __shared__ float sPr[MAXREL * 64];
    __shared__ float sb1[64], srb1[64], sq[64];
    __shared__ float sW2c0[64], sW2c1[64], sW2c2[64];
    __shared__ float sb2[3];
    __shared__ float sc0;
    int tid = threadIdx.x;
    for (int i = tid; i < NR * 64; i += blockDim.x) {
        sAr[i] = Arel[i];
        sPr[i] = Prel[i];
    }
    for (int i = tid; i < 64; i += blockDim.x) {
        sb1[i] = fpb1[i];
        srb1[i] = rtb1[i];
        sq[i] = qc[i];
        sW2c0[i] = fpW2[i * 3 + 0];
        sW2c1[i] = fpW2[i * 3 + 1];
        sW2c2[i] = fpW2[i * 3 + 2];
    }
    if (tid < 3) sb2[tid] = fpb2[tid];
    if (tid == 0) sc0 = qc[64];
    __syncthreads();

    int g = blockIdx.x * blockDim.x + tid;
    int e = g >> 4, lane = g & 15;
    if (e >= E) return;
    int h = eh[e], t = et[e], r = etype[e] - 1;

    float4 a = ((const float4*)(Ah + (size_t)h * 64))[lane];
    float4 c = ((const float4*)(At + (size_t)t * 64))[lane];
    float4 b = ((const float4*)(sAr + r * 64))[lane];
    float4 bb = ((const float4*)sb1)[lane];
    float s0 = sigm(a.x + b.x + c.x + bb.x);
    float s1 = sigm(a.y + b.y + c.y + bb.y);
    float s2 = sigm(a.z + b.z + c.z + bb.z);
    float s3 = sigm(a.w + b.w + c.w + bb.w);

    float4 w20 = ((const float4*)sW2c0)[lane];
    float4 w21 = ((const float4*)sW2c1)[lane];
    float4 w22 = ((const float4*)sW2c2)[lane];
    float z0 = s0 * w20.x + s1 * w20.y + s2 * w20.z + s3 * w20.w;
    float z1 = s0 * w21.x + s1 * w21.y + s2 * w21.z + s3 * w21.w;
    float z2 = s0 * w22.x + s1 * w22.y + s2 * w22.z + s3 * w22.w;
    z0 = red16(z0);
    z1 = red16(z1);
    z2 = red16(z2);
    z0 += sb2[0];
    z1 += sb2[1];
    z2 += sb2[2];
    float mx = fmaxf(z0, fmaxf(z1, z2));
    float e0 = __expf(z0 - mx), e1 = __expf(z1 - mx), e2 = __expf(z2 - mx);
    float inv = __fdividef(1.f, e0 + e1 + e2);
    float w0 = e0 * inv, w1 = e1 * inv, w2 = e2 * inv;

    float4 ph = ((const float4*)(P + (size_t)h * 64))[lane];
    float4 pt = ((const float4*)(P + (size_t)t * 64))[lane];
    float4 pr = ((const float4*)(sPr + r * 64))[lane];
    float4 rb = ((const float4*)srb1)[lane];
    float4 qv = ((const float4*)sq)[lane];
    float om = qv.x * sigm(w0 * ph.x + w1 * pr.x + w2 * pt.x + rb.x)
             + qv.y * sigm(w0 * ph.y + w1 * pr.y + w2 * pt.y + rb.y)
             + qv.z * sigm(w0 * ph.z + w1 * pr.z + w2 * pt.z + rb.z)
             + qv.w * sigm(w0 * ph.w + w1 * pr.w + w2 * pt.w + rb.w);
    om = red16(om);
    if (lane == 0) omegaG[posE[e]] = om + sc0;
}

// ---------------- alpha / eta in CSR order (thread per head) ----------------
__global__ void alphaeta_kernel(const float* __restrict__ omegaG, const int* __restrict__ rowE,
                                float* __restrict__ alphaG, float* __restrict__ etaG, int NE) {
    int h = blockIdx.x * blockDim.x + threadIdx.x;
    if (h >= NE) return;
    int s = rowE[h], e = rowE[h + 1];
    if (s == e) return;
    float so = 0.f;
    for (int i = s; i < e; i++) so += omegaG[i];
    float d1 = so + 1e-8f;
    float se = 0.f;
    for (int i = s; i < e; i++) {
        float a = omegaG[i] / d1;
        se += (a > GAMMA) ? a : 0.f;
    }
    float d2 = se + 1e-8f;
    for (int i = s; i < e; i++) {
        float a = omegaG[i] / d1;
        alphaG[i] = a;
        float e0 = (a > GAMMA) ? a : 0.f;
        etaG[i] = e0 / d2;
    }
}

// ---------------- merged hop kernel: 16-lane subwarp per row, float4 --------
__global__ void hop_kernel(const float* __restrict__ src, const float* __restrict__ relemb,
                           const int* __restrict__ tpackE, const float* __restrict__ rho,
                           const int* __restrict__ rowE,
                           const int* __restrict__ itemG, const float* __restrict__ wG,
                           const int* __restrict__ rowU,
                           float* __restrict__ dst, float* __restrict__ outE,
                           float* __restrict__ outU, int NE, int NU, int NR) {
    __shared__ float sRel[MAXREL * 64];
    int tid = threadIdx.x;
    for (int i = tid; i < NR * 64; i += blockDim.x) sRel[i] = relemb[i];
    __syncthreads();

    int g = blockIdx.x * blockDim.x + tid;
    int row = g >> 4, lane = g & 15;
    if (row >= NE + NU) return;
    const float4* src4 = (const float4*)src;
    const float4* sRel4 = (const float4*)sRel;

    if (row < NE) {
        int h = row;
        int s = rowE[h], e1 = rowE[h + 1];
        float4 acc = make_float4(0.f, 0.f, 0.f, 0.f);
        int i = s;
        for (; i + 2 <= e1; i += 2) {
            int tp0 = tpackE[i], tp1 = tpackE[i + 1];
            float r0 = rho[i], r1 = rho[i + 1];
            float4 x0 = src4[(size_t)(tp0 & 0xFFFFF) * 16 + lane];
            float4 x1 = src4[(size_t)(tp1 & 0xFFFFF) * 16 + lane];
            float4 w0 = sRel4[(tp0 >> 20) * 16 + lane];
            float4 w1 = sRel4[(tp1 >> 20) * 16 + lane];
            acc.x += r0 * x0.x * w0.x + r1 * x1.x * w1.x;
            acc.y += r0 * x0.y * w0.y + r1 * x1.y * w1.y;
            acc.z += r0 * x0.z * w0.z + r1 * x1.z * w1.z;
            acc.w += r0 * x0.w * w0.w + r1 * x1.w * w1.w;
        }
        if (i < e1) {
            int tp = tpackE[i];
            float rv = rho[i];
            float4 x = src4[(size_t)(tp & 0xFFFFF) * 16 + lane];
            float4 w = sRel4[(tp >> 20) * 16 + lane];
            acc.x += rv * x.x * w.x;
            acc.y += rv * x.y * w.y;
            acc.z += rv * x.z * w.z;
            acc.w += rv * x.w * w.w;
        }
        float c = fmaxf((float)(e1 - s), 1.f);
        float invc = __fdividef(1.f, c);
        acc.x *= invc; acc.y *= invc; acc.z *= invc; acc.w *= invc;
        float ss = acc.x * acc.x + acc.y * acc.y + acc.z * acc.z + acc.w * acc.w;
        ss = red16(ss);
        float inv = 1.f / fmaxf(sqrtf(ss), 1e-8f);
        float4 o;
        o.x = n2n(acc.x * inv); o.y = n2n(acc.y * inv);
        o.z = n2n(acc.z * inv); o.w = n2n(acc.w * inv);
        ((float4*)dst)[(size_t)h * 16 + lane] = o;
        float4 o2 = ((float4*)outE)[(size_t)h * 16 + lane];
        o2.x += o.x; o2.y += o.y; o2.z += o.z; o2.w += o.w;
        ((float4*)outE)[(size_t)h * 16 + lane] = o2;
    } else {
        int u = row - NE;
        int s = rowU[u], e1 = rowU[u + 1];
        float4 acc = make_float4(0.f, 0.f, 0.f, 0.f);
        int i = s;
        for (; i + 4 <= e1; i += 4) {
            int it0 = itemG[i], it1 = itemG[i + 1], it2 = itemG[i + 2], it3 = itemG[i + 3];
            float w0 = wG[i], w1 = wG[i + 1], w2 = wG[i + 2], w3 = wG[i + 3];
            float4 x0 = src4[(size_t)it0 * 16 + lane];
            float4 x1 = src4[(size_t)it1 * 16 + lane];
            float4 x2 = src4[(size_t)it2 * 16 + lane];
            float4 x3 = src4[(size_t)it3 * 16 + lane];
            acc.x += w0 * x0.x + w1 * x1.x + w2 * x2.x + w3 * x3.x;
            acc.y += w0 * x0.y + w1 * x1.y + w2 * x2.y + w3 * x3.y;
            acc.z += w0 * x0.z + w1 * x1.z + w2 * x2.z + w3 * x3.z;
            acc.w += w0 * x0.w + w1 * x1.w + w2 * x2.w + w3 * x3.w;
        }
        for (; i < e1; i++) {
            int it = itemG[i];
            float wv = wG[i];
            float4 x = src4[(size_t)it * 16 + lane];
            acc.x += wv * x.x;
            acc.y += wv * x.y;
            acc.z += wv * x.z;
            acc.w += wv * x.w;
        }
        float ss = acc.x * acc.x + acc.y * acc.y + acc.z * acc.z + acc.w * acc.w;
        ss = red16(ss);
        float inv = 1.f / fmaxf(sqrtf(ss), 1e-8f);
        float4 o;
        o.x = n2n(acc.x * inv); o.y = n2n(acc.y * inv);
        o.z = n2n(acc.z * inv); o.w = n2n(acc.w * inv);
        float4 o2 = ((float4*)outU)[(size_t)u * 16 + lane];
        o2.x += o.x; o2.y += o.y; o2.z += o.z; o2.w += o.w;
        ((float4*)outU)[(size_t)u * 16 + lane] = o2;
    }
}

// ---------------- launch ----------------
extern "C" void kernel_launch(void* const* d_in, const int* in_sizes, int n_in,
                              void* d_out, int out_size) {
    const float* user_embed = (const float*)d_in[0];
    const float* item_embed = (const float*)d_in[1];
    const float* Wq = (const float*)d_in[2];
    const float* Wk = (const float*)d_in[3];
    const float* Wv = (const float*)d_in[4];
    const float* ent_real = (const float*)d_in[5];
    const float* ent_imag = (const float*)d_in[6];
    const float* rel_real = (const float*)d_in[7];
    const float* rel_imag = (const float*)d_in[8];
    const float* fp_W1 = (const float*)d_in[9];
    const float* fp_b1 = (const float*)d_in[10];
    const float* fp_W2 = (const float*)d_in[11];
    const float* fp_b2 = (const float*)d_in[12];
    const float* rt_W1 = (const float*)d_in[13];
    const float* rt_b1 = (const float*)d_in[14];
    const float* rt_W2 = (const float*)d_in[15];
    const float* rt_b2 = (const float*)d_in[16];
    const float* relation_emb = (const float*)d_in[17];
    const float* user_emb = (const float*)d_in[18];
    const float* entity_emb = (const float*)d_in[19];
    const float* inter_edge_w = (const float*)d_in[20];
    const int* edge_index = (const int*)d_in[21];
    const int* edge_type = (const int*)d_in[22];
    const int* inter_edge = (const int*)d_in[23];
    float* out = (float*)d_out;

    int NU = in_sizes[0] / D;
    int NI = in_sizes[1] / D;
    int NE = in_sizes[5] / KD;
    int NR = in_sizes[7] / KD;
    int E = in_sizes[22];
    int EI = in_sizes[20];
    const int* eh = edge_index;
    const int* et = edge_index + E;
    const int* users = inter_edge;
    const int* items = inter_edge + EI;

    float *userWq, *itemWk, *itemWv, *scoresG, *itemCoeff, *pref, *qc;
    float *omegaG, *alphaG, *etaG, *embA, *embB, *wG;
    float *Ah, *At, *P, *Arel, *Prel;
    int *degE, *rowE, *curE, *posE, *tpackE, *degU, *rowU, *curU, *posU, *itemG;
    cudaGetSymbolAddress((void**)&userWq, g_userWq);
    cudaGetSymbolAddress((void**)&itemWk, g_itemWk);
    cudaGetSymbolAddress((void**)&itemWv, g_itemWv);
    cudaGetSymbolAddress((void**)&scoresG, g_scoresG);
    cudaGetSymbolAddress((void**)&itemCoeff, g_itemCoeff);
    cudaGetSymbolAddress((void**)&pref, g_pref);
    cudaGetSymbolAddress((void**)&qc, g_qc);
    cudaGetSymbolAddress((void**)&omegaG, g_omegaG);
    cudaGetSymbolAddress((void**)&alphaG, g_alphaG);
    cudaGetSymbolAddress((void**)&etaG, g_etaG);
    cudaGetSymbolAddress((void**)&embA, g_embA);
    cudaGetSymbolAddress((void**)&embB, g_embB);
    cudaGetSymbolAddress((void**)&degE, g_degE);
    cudaGetSymbolAddress((void**)&rowE, g_rowE);
    cudaGetSymbolAddress((void**)&curE, g_curE);
    cudaGetSymbolAddress((void**)&posE, g_posE);
    cudaGetSymbolAddress((void**)&tpackE, g_tpackE);
    cudaGetSymbolAddress((void**)&degU, g_degU);
    cudaGetSymbolAddress((void**)&rowU, g_rowU);
    cudaGetSymbolAddress((void**)&curU, g_curU);
    cudaGetSymbolAddress((void**)&posU, g_posU);
    cudaGetSymbolAddress((void**)&itemG, g_itemG);
    cudaGetSymbolAddress((void**)&wG, g_wG);
    cudaGetSymbolAddress((void**)&Ah, g_Ah);
    cudaGetSymbolAddress((void**)&At, g_At);
    cudaGetSymbolAddress((void**)&P, g_P);
    cudaGetSymbolAddress((void**)&Arel, g_Arel);
    cudaGetSymbolAddress((void**)&Prel, g_Prel);

    // 1: init output (base embeddings)
    {
        int tot = (NE + NU) * 16;
        out_init_kernel<<<(tot + 255) / 256, 256>>>((float4*)out, (const float4*)entity_emb,
                                                    (const float4*)user_emb, NE * 16, NU * 16);
    }
    // 2
    zero_kernel<<<(NE + 255) / 256, 256>>>(degE, degU, itemCoeff, pref, NE, NU, NI);
    // 3
    hist2_kernel<<<(E + EI + 255) / 256, 256>>>(eh, users, degE, degU, E, EI);
    // 4
    exscan2_kernel<<<2, 1024>>>(degE, rowE, NE, degU, rowU, NU);
    // 5
    copy2_kernel<<<(NE + 255) / 256, 256>>>(rowE, curE, NE, rowU, curU, NU);
    // 6 (profiled slot)
    entpre_kernel<<<(NE + 31) / 32, 1024>>>(ent_real, ent_imag, fp_W1, rt_W1, Ah, At, P, NE);
    // 7
    fill2_kernel<<<(E + EI + 255) / 256, 256>>>(eh, et, edge_type, curE, posE, tpackE, E,
                                                users, items, inter_edge_w, curU, posU,
                                                itemG, wG, EI);
    // 8
    relpre_kernel<<<1, NR * 64>>>(rel_real, rel_imag, fp_W1, rt_W1, Arel, Prel, NR);
    // 9-11
    gemm64_kernel<<<(NU + 15) / 16, 1024>>>(user_embed, Wq, userWq, NU);
    gemm64_kernel<<<(NI + 15) / 16, 1024>>>(item_embed, Wk, itemWk, NI);
    gemm64_kernel<<<(NI + 15) / 16, 1024>>>(item_embed, Wv, itemWv, NI);
    // 12
    {
        long long th = (long long)EI * 16;
        score_kernel<<<(int)((th + 255) / 256), 256>>>(userWq, itemWk, users, items,
                                                       inter_edge_w, posU, scoresG, EI);
    }
    // 13
    {
        long long th = (long long)NU * 32;
        usoftmax_kernel<<<(int)((th + 255) / 256), 256>>>(scoresG, itemG, rowU, itemCoeff, NU);
    }
    // 14-15
    pref_kernel<<<256, 64>>>(itemCoeff, itemWv, pref, NI);
    qc_kernel<<<1, 64>>>(rt_W2, rt_b2, pref, qc);
    // 16
    {
        long long th = (long long)E * 16;
        omega_kernel<<<(int)((th + 255) / 256), 256>>>(Ah, At, P, Arel, Prel, eh, et, edge_type,
                                                       fp_b1, fp_W2, fp_b2, rt_b1, qc, posE,
                                                       omegaG, NR, E);
    }
    // 17
    alphaeta_kernel<<<(NE + 255) / 256, 256>>>(omegaG, rowE, alphaG, etaG, NE);

    // 18-20: 3-hop graph conv
    const float* srcs[3] = {entity_emb, embA, embB};
    float* dsts[3] = {embA, embB, embA};
    const float* rhos[3] = {alphaG, alphaG, etaG};
    for (int hop = 0; hop < 3; hop++) {
        long long th = (long long)(NE + NU) * 16;
        hop_kernel<<<(int)((th + 255) / 256), 256>>>(
            srcs[hop], relation_emb, tpackE, rhos[hop], rowE, itemG, wG, rowU,
            dsts[hop], out, out + (size_t)NE * D, NE, NU, NR);
    }
}

// round 5
// speedup vs baseline: 2.7050x; 1.1108x over previous
#include <cuda_runtime.h>
#include <math.h>

#define D 64
#define KD 32
#define MAXU 50000
#define MAXI 30000
#define MAXENT 100000
#define MAXE 500000
#define MAXEI 1000000
#define MAXREL 10
#define GAMMA 0.2f
#define SCHUNK 1024

typedef unsigned long long u64;

// ---------------- scratch (device globals; no allocation) ----------------
__device__ float g_userWq[MAXU * D];
__device__ float g_itemWk[MAXI * D];
__device__ float g_itemWv[MAXI * D];
__device__ float g_scoresG[MAXEI];
__device__ float g_itemCoeff[MAXI];
__device__ float g_pref[D];
__device__ float g_qc[D + 1];
__device__ float g_omegaG[MAXE];
__device__ float g_alphaG[MAXE];
__device__ float g_etaG[MAXE];
__device__ float g_embA[MAXENT * D];
__device__ float g_embB[MAXENT * D];
__device__ int g_degE[MAXENT];
__device__ int g_rowE[MAXENT + 1];
__device__ int g_curE[MAXENT];
__device__ int g_posE[MAXE];
__device__ int g_tpackE[MAXE];
__device__ int g_degU[MAXU];
__device__ int g_rowU[MAXU + 1];
__device__ int g_curU[MAXU];
__device__ int g_posU[MAXEI];
__device__ int g_itemG[MAXEI];
__device__ float g_wG[MAXEI];
__device__ int g_bsum[1024];
__device__ int g_boff[1024];
// precomputed per-entity tables
__device__ float g_Ah[MAXENT * D];
__device__ float g_At[MAXENT * D];
__device__ float g_P[MAXENT * D];
__device__ float g_Arel[MAXREL * D];
__device__ float g_Prel[MAXREL * D];

// ---------------- helpers ----------------
__device__ __forceinline__ float n2n(float x) {
    if (x != x) return 0.f;
    if (x == INFINITY) return 1e4f;
    if (x == -INFINITY) return 1e-4f;
    return x;
}
__device__ __forceinline__ float sigm(float x) {
    return __fdividef(1.f, 1.f + __expf(-x));
}
__device__ __forceinline__ u64 pack2(float x, float y) {
    u64 r;
    asm("mov.b64 %0, {%1, %2};" : "=l"(r) : "f"(x), "f"(y));
    return r;
}
__device__ __forceinline__ u64 ffma2(u64 a, u64 b, u64 c) {
    u64 d;
    asm("fma.rn.f32x2 %0, %1, %2, %3;" : "=l"(d) : "l"(a), "l"(b), "l"(c));
    return d;
}
__device__ __forceinline__ float red16(float v) {
#pragma unroll
    for (int o = 8; o; o >>= 1) v += __shfl_xor_sync(0xffffffffu, v, o);
    return v;
}

// ---------------- init ----------------
__global__ void zero_kernel(int* degE, int* degU, float* ic, float* pref,
                            int NE, int NU, int NI) {
    int i = blockIdx.x * blockDim.x + threadIdx.x;
    if (i < NE) degE[i] = 0;
    if (i < NU) degU[i] = 0;
    if (i < NI) ic[i] = 0.f;
    if (i < 64) pref[i] = 0.f;
}

__global__ void hist2_kernel(const int* __restrict__ eh, const int* __restrict__ users,
                             int* degE, int* degU, int E, int EI) {
    int i = blockIdx.x * blockDim.x + threadIdx.x;
    if (i < E) atomicAdd(&degE[eh[i]], 1);
    else if (i < E + EI) atomicAdd(&degU[users[i - E]], 1);
}

// ---------------- 3-phase parallel exclusive scan (E and U fused) ----------
__global__ void bsum_kernel(const int* __restrict__ degE, int NE,
                            const int* __restrict__ degU, int NU,
                            int* bsum, int nBE) {
    __shared__ int wsum[32];
    int b = blockIdx.x;
    bool isE = b < nBE;
    const int* deg = isE ? degE : degU;
    int n = isE ? NE : NU;
    int base = (isE ? b : (b - nBE)) * SCHUNK;
    int i = base + threadIdx.x;
    int v = (i < n) ? deg[i] : 0;
    int lane = threadIdx.x & 31, wid = threadIdx.x >> 5;
#pragma unroll
    for (int o = 16; o; o >>= 1) v += __shfl_xor_sync(0xffffffffu, v, o);
    if (lane == 0) wsum[wid] = v;
    __syncthreads();
    if (wid == 0) {
        int s = wsum[lane];
#pragma unroll
        for (int o = 16; o; o >>= 1) s += __shfl_xor_sync(0xffffffffu, s, o);
        if (lane == 0) bsum[b] = s;
    }
}

__global__ void bscan_kernel(const int* __restrict__ bsum, int* boff, int nBE, int nB,
                             int* rowE, int NE, int* rowU, int NU) {
    __shared__ int sh[1024];
    int tid = threadIdx.x;
    for (int i = tid; i < nB; i += blockDim.x) sh[i] = bsum[i];
    __syncthreads();
    if (tid == 0) {
        int acc = 0;
        for (int i = 0; i < nBE; i++) { int v = sh[i]; sh[i] = acc; acc += v; }
        rowE[NE] = acc;
    }
    if (tid == 1) {
        int acc = 0;
        for (int i = nBE; i < nB; i++) { int v = sh[i]; sh[i] = acc; acc += v; }
        rowU[NU] = acc;
    }
    __syncthreads();
    for (int i = tid; i < nB; i += blockDim.x) boff[i] = sh[i];
}

__global__ void bexpand_kernel(const int* __restrict__ degE, int NE,
                               const int* __restrict__ degU, int NU,
                               const int* __restrict__ boff, int nBE,
                               int* rowE, int* rowU, int* curE, int* curU) {
    __shared__ int wsum[32];
    int b = blockIdx.x;
    bool isE = b < nBE;
    const int* deg = isE ? degE : degU;
    int n = isE ? NE : NU;
    int* row = isE ? rowE : rowU;
    int* cur = isE ? curE : curU;
    int base = (isE ? b : (b - nBE)) * SCHUNK;
    int i = base + threadIdx.x;
    int v = (i < n) ? deg[i] : 0;
    int lane = threadIdx.x & 31, wid = threadIdx.x >> 5;
    int s = v;
#pragma unroll
    for (int o = 1; o < 32; o <<= 1) {
        int t = __shfl_up_sync(0xffffffffu, s, o);
        if (lane >= o) s += t;
    }
    if (lane == 31) wsum[wid] = s;
    __syncthreads();
    if (wid == 0) {
        int ws = wsum[lane];
#pragma unroll
        for (int o = 1; o < 32; o <<= 1) {
            int t = __shfl_up_sync(0xffffffffu, ws, o);
            if (lane >= o) ws += t;
        }
        wsum[lane] = ws;
    }
    __syncthreads();
    int excl = ((wid == 0) ? 0 : wsum[wid - 1]) + s - v + boff[b];
    if (i < n) {
        row[i] = excl;
        cur[i] = excl;
    }
}

__global__ void fill2_kernel(const int* __restrict__ eh, const int* __restrict__ et,
                             const int* __restrict__ etype, int* curE, int* posE, int* tpackE,
                             int E,
                             const int* __restrict__ users, const int* __restrict__ items,
                             const float* __restrict__ w, int* curU, int* posU,
                             int* itemG, float* wG, int EI) {
    int i = blockIdx.x * blockDim.x + threadIdx.x;
    if (i < E) {
        int p = atomicAdd(&curE[eh[i]], 1);
        posE[i] = p;
        tpackE[p] = et[i] | ((etype[i] - 1) << 20);
    } else if (i < E + EI) {
        int e = i - E;
        int p = atomicAdd(&curU[users[e]], 1);
        posU[e] = p;
        itemG[p] = items[e];
        wG[p] = w[e];
    }
}

// ---------------- entity precompute: Ah, At, P ----------------
__global__ void entpre_kernel(const float* __restrict__ ent_real,
                              const float* __restrict__ ent_imag,
                              const float* __restrict__ fpW1,
                              const float* __restrict__ rtW1,
                              float* __restrict__ Ah, float* __restrict__ At,
                              float* __restrict__ P, int NE) {
    __shared__ float sWa[64 * 64];
    __shared__ float sWb[64 * 64];
    __shared__ float sWp[64 * 64];
    __shared__ float sX[32 * 64];
    int tid = threadIdx.x;  // 1024
    for (int i = tid; i < 4096; i += 1024) {
        sWa[i] = fpW1[i];
        sWb[i] = fpW1[128 * 64 + i];
        sWp[i] = rtW1[i];
    }
    int rowBase = blockIdx.x * 32;
    for (int i = tid; i < 32 * 64; i += 1024) {
        int rl = i >> 6, k = i & 63;
        int n = rowBase + rl;
        float v = 0.f;
        if (n < NE) v = (k < 32) ? ent_real[n * KD + k] : ent_imag[n * KD + (k - 32)];
        sX[i] = v;
    }
    __syncthreads();
    int rl = tid >> 5, jp = tid & 31;
    int n = rowBase + rl;
    if (n >= NE) return;
    u64 a0 = 0, a1 = 0, a2 = 0;
    const u64* wa = (const u64*)sWa;
    const u64* wb = (const u64*)sWb;
    const u64* wp = (const u64*)sWp;
#pragma unroll 8
    for (int k = 0; k < 64; k++) {
        float xv = sX[rl * 64 + k];
        u64 xx = pack2(xv, xv);
        a0 = ffma2(xx, wa[k * 32 + jp], a0);
        a1 = ffma2(xx, wb[k * 32 + jp], a1);
        a2 = ffma2(xx, wp[k * 32 + jp], a2);
    }
    ((u64*)Ah)[n * 32 + jp] = a0;
    ((u64*)At)[n * 32 + jp] = a1;
    ((u64*)P)[n * 32 + jp] = a2;
}

// ---------------- relation precompute ----------------
__global__ void relpre_kernel(const float* __restrict__ rel_real,
                              const float* __restrict__ rel_imag,
                              const float* __restrict__ fpW1,
                              const float* __restrict__ rtW1,
                              float* __restrict__ Arel, float* __restrict__ Prel, int NR) {
    int tid = threadIdx.x;
    int r = tid >> 6, j = tid & 63;
    if (r >= NR) return;
    float a = 0.f, p = 0.f;
    for (int k = 0; k < 64; k++) {
        float xv = (k < 32) ? rel_real[r * KD + k] : rel_imag[r * KD + (k - 32)];
        a += xv * fpW1[(64 + k) * 64 + j];
        p += xv * rtW1[k * 64 + j];
    }
    Arel[r * 64 + j] = a;
    Prel[r * 64 + j] = p;
}

// ---------------- small GEMM: Y[n,64] = X[n,64] @ W[64,64] ----------------
__global__ void gemm64_kernel(const float* __restrict__ X, const float* __restrict__ W,
                              float* __restrict__ Y, int nrows) {
    __shared__ float sW[64 * 64];
    __shared__ float sX[16 * 64];
    int tid = threadIdx.x;
    for (int i = tid; i < 4096; i += 1024) sW[i] = W[i];
    int r = tid >> 6, j = tid & 63;
    int row = blockIdx.x * 16 + r;
    if (row < nrows) sX[r * 64 + j] = X[row * 64 + j];
    __syncthreads();
    if (row < nrows) {
        float acc = 0.f;
#pragma unroll
        for (int k = 0; k < 64; k++) acc += sX[r * 64 + k] * sW[k * 64 + j];
        Y[row * 64 + j] = acc;
    }
}

// ---------------- miner: 16-lane subwarp per edge ----------------
__global__ void score_kernel(const float* __restrict__ uq, const float* __restrict__ ik,
                             const int* __restrict__ users, const int* __restrict__ items,
                             const float* __restrict__ w, const int* __restrict__ posU,
                             float* __restrict__ scoresG, int EI) {
    int g = blockIdx.x * blockDim.x + threadIdx.x;
    int e = g >> 4, lane = g & 15;
    if (e >= EI) return;
    int u = users[e], it = items[e];
    float4 q = ((const float4*)uq)[u * 16 + lane];
    float4 k = ((const float4*)ik)[it * 16 + lane];
    float p = q.x * k.x + q.y * k.y + q.z * k.z + q.w * k.w;
    p = red16(p);
    if (lane == 0) scoresG[posU[e]] = p * 0.125f * w[e];
}

__global__ void usoftmax_kernel(const float* __restrict__ scoresG, const int* __restrict__ itemG,
                                const int* __restrict__ rowU, float* itemCoeff, int NU) {
    int g = blockIdx.x * blockDim.x + threadIdx.x;
    int u = g >> 5, lane = g & 31;
    if (u >= NU) return;
    int s = rowU[u], e = rowU[u + 1];
    int deg = e - s;
    if (deg == 0) return;
    float m = -INFINITY;
    for (int i = s + lane; i < e; i += 32) m = fmaxf(m, scoresG[i]);
#pragma unroll
    for (int o = 16; o; o >>= 1) m = fmaxf(m, __shfl_xor_sync(0xffffffffu, m, o));
    float den = 0.f;
    for (int i = s + lane; i < e; i += 32) den += __expf(scoresG[i] - m);
#pragma unroll
    for (int o = 16; o; o >>= 1) den += __shfl_xor_sync(0xffffffffu, den, o);
    float invc = __fdividef(1.f, den * fmaxf((float)deg, 1.f));
    for (int i = s + lane; i < e; i += 32)
        atomicAdd(&itemCoeff[itemG[i]], __expf(scoresG[i] - m) * invc);
}

__global__ void pref_kernel(const float* __restrict__ itemCoeff,
                            const float* __restrict__ itemWv, float* pref, int NI) {
    int j = threadIdx.x;  // 64
    float acc = 0.f;
    for (int i = blockIdx.x; i < NI; i += gridDim.x)
        acc += itemCoeff[i] * itemWv[i * 64 + j];
    atomicAdd(&pref[j], acc);
}

__global__ void qc_kernel(const float* __restrict__ rtW2, const float* __restrict__ rtb2,
                          const float* __restrict__ pref, float* qc) {
    __shared__ float sp[64];
    __shared__ float red[64];
    int j = threadIdx.x;
    sp[j] = pref[j];
    __syncthreads();
    float q = 0.f;
#pragma unroll
    for (int k = 0; k < 64; k++) q += rtW2[j * 64 + k] * sp[k];
    qc[j] = q * 0.125f;
    red[j] = rtb2[j] * sp[j];
    __syncthreads();
    if (j == 0) {
        float c = 0.f;
        for (int k = 0; k < 64; k++) c += red[k];
        qc[64] = c * 0.125f;
    }
}

// ---------------- omega: 16-lane subwarp per edge ----------------
__global__ void omega_kernel(const float* __restrict__ Ah, const float* __restrict__ At,
                             const float* __restrict__ P,
                             const float* __restrict__ Arel, const float* __restrict__ Prel,
                             const int* __restrict__ eh, const int* __restrict__ et,
                             const int* __restrict__ etype,
                             const float* __restrict__ fpb1, const float* __restrict__ fpW2,
                             const float* __restrict__ fpb2, const float* __restrict__ rtb1,
                             const float* __restrict__ qc, const int* __restrict__ posE,
                             float* __restrict__ omegaG, int NR, int E) {
    __shared__ float sAr[MAXREL * 64];
    __shared__ float sPr[MAXREL * 64];
    __shared__ float sb1[64], srb1[64], sq[64];
    __shared__ float sW2c0[64], sW2c1[64], sW2c2[64];
    __shared__ float sb2[3];
    __shared__ float sc0;
    int tid = threadIdx.x;
    for (int i = tid; i < NR * 64; i += blockDim.x) {
        sAr[i] = Arel[i];
        sPr[i] = Prel[i];
    }
    for (int i = tid; i < 64; i += blockDim.x) {
        sb1[i] = fpb1[i];
        srb1[i] = rtb1[i];
        sq[i] = qc[i];
        sW2c0[i] = fpW2[i * 3 + 0];
        sW2c1[i] = fpW2[i * 3 + 1];
        sW2c2[i] = fpW2[i * 3 + 2];
    }
    if (tid < 3) sb2[tid] = fpb2[tid];
    if (tid == 0) sc0 = qc[64];
    __syncthreads();

    int g = blockIdx.x * blockDim.x + tid;
    int e = g >> 4, lane = g & 15;
    if (e >= E) return;
    int h = eh[e], t = et[e], r = etype[e] - 1;

    float4 a = ((const float4*)(Ah + (size_t)h * 64))[lane];
    float4 c = ((const float4*)(At + (size_t)t * 64))[lane];
    float4 b = ((const float4*)(sAr + r * 64))[lane];
    float4 bb = ((const float4*)sb1)[lane];
    float s0 = sigm(a.x + b.x + c.x + bb.x);
    float s1 = sigm(a.y + b.y + c.y + bb.y);
    float s2 = sigm(a.z + b.z + c.z + bb.z);
    float s3 = sigm(a.w + b.w + c.w + bb.w);

    float4 w20 = ((const float4*)sW2c0)[lane];
    float4 w21 = ((const float4*)sW2c1)[lane];
    float4 w22 = ((const float4*)sW2c2)[lane];
    float z0 = s0 * w20.x + s1 * w20.y + s2 * w20.z + s3 * w20.w;
    float z1 = s0 * w21.x + s1 * w21.y + s2 * w21.z + s3 * w21.w;
    float z2 = s0 * w22.x + s1 * w22.y + s2 * w22.z + s3 * w22.w;
    z0 = red16(z0);
    z1 = red16(z1);
    z2 = red16(z2);
    z0 += sb2[0];
    z1 += sb2[1];
    z2 += sb2[2];
    float mx = fmaxf(z0, fmaxf(z1, z2));
    float e0 = __expf(z0 - mx), e1 = __expf(z1 - mx), e2 = __expf(z2 - mx);
    float inv = __fdividef(1.f, e0 + e1 + e2);
    float w0 = e0 * inv, w1 = e1 * inv, w2 = e2 * inv;

    float4 ph = ((const float4*)(P + (size_t)h * 64))[lane];
    float4 pt = ((const float4*)(P + (size_t)t * 64))[lane];
    float4 pr = ((const float4*)(sPr + r * 64))[lane];
    float4 rb = ((const float4*)srb1)[lane];
    float4 qv = ((const float4*)sq)[lane];
    float om = qv.x * sigm(w0 * ph.x + w1 * pr.x + w2 * pt.x + rb.x)
             + qv.y * sigm(w0 * ph.y + w1 * pr.y + w2 * pt.y + rb.y)
             + qv.z * sigm(w0 * ph.z + w1 * pr.z + w2 * pt.z + rb.z)
             + qv.w * sigm(w0 * ph.w + w1 * pr.w + w2 * pt.w + rb.w);
    om = red16(om);
    if (lane == 0) omegaG[posE[e]] = om + sc0;
}

// ---------------- alpha / eta in CSR order ----------------
__global__ void alphaeta_kernel(const float* __restrict__ omegaG, const int* __restrict__ rowE,
                                float* __restrict__ alphaG, float* __restrict__ etaG, int NE) {
    int h = blockIdx.x * blockDim.x + threadIdx.x;
    if (h >= NE) return;
    int s = rowE[h], e = rowE[h + 1];
    if (s == e) return;
    float so = 0.f;
    for (int i = s; i < e; i++) so += omegaG[i];
    float d1 = so + 1e-8f;
    float se = 0.f;
    for (int i = s; i < e; i++) {
        float a = omegaG[i] / d1;
        se += (a > GAMMA) ? a : 0.f;
    }
    float d2 = se + 1e-8f;
    for (int i = s; i < e; i++) {
        float a = omegaG[i] / d1;
        alphaG[i] = a;
        float e0 = (a > GAMMA) ? a : 0.f;
        etaG[i] = e0 / d2;
    }
}

// ---------------- merged hop kernel: 16-lane subwarp per row -------------
// hop0: out = base + normalized ; else: out += normalized
__global__ void hop_kernel(const float* __restrict__ src, const float* __restrict__ relemb,
                           const int* __restrict__ tpackE, const float* __restrict__ rho,
                           const int* __restrict__ rowE,
                           const int* __restrict__ itemG, const float* __restrict__ wG,
                           const int* __restrict__ rowU,
                           float* __restrict__ dst, float* __restrict__ outE,
                           float* __restrict__ outU,
                           const float* __restrict__ baseE, const float* __restrict__ baseU,
                           int hop0, int NE, int NU, int NR) {
    __shared__ float sRel[MAXREL * 64];
    int tid = threadIdx.x;
    for (int i = tid; i < NR * 64; i += blockDim.x) sRel[i] = relemb[i];
    __syncthreads();

    int g = blockIdx.x * blockDim.x + tid;
    int row = g >> 4, lane = g & 15;
    if (row >= NE + NU) return;
    const float4* src4 = (const float4*)src;
    const float4* sRel4 = (const float4*)sRel;

    if (row < NE) {
        int h = row;
        int s = rowE[h], e1 = rowE[h + 1];
        float4 acc = make_float4(0.f, 0.f, 0.f, 0.f);
        int i = s;
        for (; i + 2 <= e1; i += 2) {
            int tp0 = tpackE[i], tp1 = tpackE[i + 1];
            float r0 = rho[i], r1 = rho[i + 1];
            float4 x0 = src4[(size_t)(tp0 & 0xFFFFF) * 16 + lane];
            float4 x1 = src4[(size_t)(tp1 & 0xFFFFF) * 16 + lane];
            float4 w0 = sRel4[(tp0 >> 20) * 16 + lane];
            float4 w1 = sRel4[(tp1 >> 20) * 16 + lane];
            acc.x += r0 * x0.x * w0.x + r1 * x1.x * w1.x;
            acc.y += r0 * x0.y * w0.y + r1 * x1.y * w1.y;
            acc.z += r0 * x0.z * w0.z + r1 * x1.z * w1.z;
            acc.w += r0 * x0.w * w0.w + r1 * x1.w * w1.w;
        }
        if (i < e1) {
            int tp = tpackE[i];
            float rv = rho[i];
            float4 x = src4[(size_t)(tp & 0xFFFFF) * 16 + lane];
            float4 w = sRel4[(tp >> 20) * 16 + lane];
            acc.x += rv * x.x * w.x;
            acc.y += rv * x.y * w.y;
            acc.z += rv * x.z * w.z;
            acc.w += rv * x.w * w.w;
        }
        float c = fmaxf((float)(e1 - s), 1.f);
        float invc = __fdividef(1.f, c);
        acc.x *= invc; acc.y *= invc; acc.z *= invc; acc.w *= invc;
        float ss = acc.x * acc.x + acc.y * acc.y + acc.z * acc.z + acc.w * acc.w;
        ss = red16(ss);
        float inv = 1.f / fmaxf(sqrtf(ss), 1e-8f);
        float4 o;
        o.x = n2n(acc.x * inv); o.y = n2n(acc.y * inv);
        o.z = n2n(acc.z * inv); o.w = n2n(acc.w * inv);
        ((float4*)dst)[(size_t)h * 16 + lane] = o;
        float4 o2 = hop0 ? ((const float4*)baseE)[(size_t)h * 16 + lane]
                         : ((float4*)outE)[(size_t)h * 16 + lane];
        o2.x += o.x; o2.y += o.y; o2.z += o.z; o2.w += o.w;
        ((float4*)outE)[(size_t)h * 16 + lane] = o2;
    } else {
        int u = row - NE;
        int s = rowU[u], e1 = rowU[u + 1];
        float4 acc = make_float4(0.f, 0.f, 0.f, 0.f);
        int i = s;
        for (; i + 4 <= e1; i += 4) {
            int it0 = itemG[i], it1 = itemG[i + 1], it2 = itemG[i + 2], it3 = itemG[i + 3];
            float w0 = wG[i], w1 = wG[i + 1], w2 = wG[i + 2], w3 = wG[i + 3];
            float4 x0 = src4[(size_t)it0 * 16 + lane];
            float4 x1 = src4[(size_t)it1 * 16 + lane];
            float4 x2 = src4[(size_t)it2 * 16 + lane];
            float4 x3 = src4[(size_t)it3 * 16 + lane];
            acc.x += w0 * x0.x + w1 * x1.x + w2 * x2.x + w3 * x3.x;
            acc.y += w0 * x0.y + w1 * x1.y + w2 * x2.y + w3 * x3.y;
            acc.z += w0 * x0.z + w1 * x1.z + w2 * x2.z + w3 * x3.z;
            acc.w += w0 * x0.w + w1 * x1.w + w2 * x2.w + w3 * x3.w;
        }
        for (; i < e1; i++) {
            int it = itemG[i];
            float wv = wG[i];
            float4 x = src4[(size_t)it * 16 + lane];
            acc.x += wv * x.x;
            acc.y += wv * x.y;
            acc.z += wv * x.z;
            acc.w += wv * x.w;
        }
        float ss = acc.x * acc.x + acc.y * acc.y + acc.z * acc.z + acc.w * acc.w;
        ss = red16(ss);
        float inv = 1.f / fmaxf(sqrtf(ss), 1e-8f);
        float4 o;
        o.x = n2n(acc.x * inv); o.y = n2n(acc.y * inv);
        o.z = n2n(acc.z * inv); o.w = n2n(acc.w * inv);
        float4 o2 = hop0 ? ((const float4*)baseU)[(size_t)u * 16 + lane]
                         : ((float4*)outU)[(size_t)u * 16 + lane];
        o2.x += o.x; o2.y += o.y; o2.z += o.z; o2.w += o.w;
        ((float4*)outU)[(size_t)u * 16 + lane] = o2;
    }
}

// ---------------- launch ----------------
extern "C" void kernel_launch(void* const* d_in, const int* in_sizes, int n_in,
                              void* d_out, int out_size) {
    const float* user_embed = (const float*)d_in[0];
    const float* item_embed = (const float*)d_in[1];
    const float* Wq = (const float*)d_in[2];
    const float* Wk = (const float*)d_in[3];
    const float* Wv = (const float*)d_in[4];
    const float* ent_real = (const float*)d_in[5];
    const float* ent_imag = (const float*)d_in[6];
    const float* rel_real = (const float*)d_in[7];
    const float* rel_imag = (const float*)d_in[8];
    const float* fp_W1 = (const float*)d_in[9];
    const float* fp_b1 = (const float*)d_in[10];
    const float* fp_W2 = (const float*)d_in[11];
    const float* fp_b2 = (const float*)d_in[12];
    const float* rt_W1 = (const float*)d_in[13];
    const float* rt_b1 = (const float*)d_in[14];
    const float* rt_W2 = (const float*)d_in[15];
    const float* rt_b2 = (const float*)d_in[16];
    const float* relation_emb = (const float*)d_in[17];
    const float* user_emb = (const float*)d_in[18];
    const float* entity_emb = (const float*)d_in[19];
    const float* inter_edge_w = (const float*)d_in[20];
    const int* edge_index = (const int*)d_in[21];
    const int* edge_type = (const int*)d_in[22];
    const int* inter_edge = (const int*)d_in[23];
    float* out = (float*)d_out;

    int NU = in_sizes[0] / D;
    int NI = in_sizes[1] / D;
    int NE = in_sizes[5] / KD;
    int NR = in_sizes[7] / KD;
    int E = in_sizes[22];
    int EI = in_sizes[20];
    const int* eh = edge_index;
    const int* et = edge_index + E;
    const int* users = inter_edge;
    const int* items = inter_edge + EI;

    float *userWq, *itemWk, *itemWv, *scoresG, *itemCoeff, *pref, *qc;
    float *omegaG, *alphaG, *etaG, *embA, *embB, *wG;
    float *Ah, *At, *P, *Arel, *Prel;
    int *degE, *rowE, *curE, *posE, *tpackE, *degU, *rowU, *curU, *posU, *itemG;
    int *bsum, *boff;
    cudaGetSymbolAddress((void**)&userWq, g_userWq);
    cudaGetSymbolAddress((void**)&itemWk, g_itemWk);
    cudaGetSymbolAddress((void**)&itemWv, g_itemWv);
    cudaGetSymbolAddress((void**)&scoresG, g_scoresG);
    cudaGetSymbolAddress((void**)&itemCoeff, g_itemCoeff);
    cudaGetSymbolAddress((void**)&pref, g_pref);
    cudaGetSymbolAddress((void**)&qc, g_qc);
    cudaGetSymbolAddress((void**)&omegaG, g_omegaG);
    cudaGetSymbolAddress((void**)&alphaG, g_alphaG);
    cudaGetSymbolAddress((void**)&etaG, g_etaG);
    cudaGetSymbolAddress((void**)&embA, g_embA);
    cudaGetSymbolAddress((void**)&embB, g_embB);
    cudaGetSymbolAddress((void**)&degE, g_degE);
    cudaGetSymbolAddress((void**)&rowE, g_rowE);
    cudaGetSymbolAddress((void**)&curE, g_curE);
    cudaGetSymbolAddress((void**)&posE, g_posE);
    cudaGetSymbolAddress((void**)&tpackE, g_tpackE);
    cudaGetSymbolAddress((void**)&degU, g_degU);
    cudaGetSymbolAddress((void**)&rowU, g_rowU);
    cudaGetSymbolAddress((void**)&curU, g_curU);
    cudaGetSymbolAddress((void**)&posU, g_posU);
    cudaGetSymbolAddress((void**)&itemG, g_itemG);
    cudaGetSymbolAddress((void**)&wG, g_wG);
    cudaGetSymbolAddress((void**)&bsum, g_bsum);
    cudaGetSymbolAddress((void**)&boff, g_boff);
    cudaGetSymbolAddress((void**)&Ah, g_Ah);
    cudaGetSymbolAddress((void**)&At, g_At);
    cudaGetSymbolAddress((void**)&P, g_P);
    cudaGetSymbolAddress((void**)&Arel, g_Arel);
    cudaGetSymbolAddress((void**)&Prel, g_Prel);

    int nBE = (NE + SCHUNK - 1) / SCHUNK;
    int nBU = (NU + SCHUNK - 1) / SCHUNK;
    int nB = nBE + nBU;

    zero_kernel<<<(NE + 255) / 256, 256>>>(degE, degU, itemCoeff, pref, NE, NU, NI);
    hist2_kernel<<<(E + EI + 255) / 256, 256>>>(eh, users, degE, degU, E, EI);
    bsum_kernel<<<nB, SCHUNK>>>(degE, NE, degU, NU, bsum, nBE);
    bscan_kernel<<<1, 256>>>(bsum, boff, nBE, nB, rowE, NE, rowU, NU);
    bexpand_kernel<<<nB, SCHUNK>>>(degE, NE, degU, NU, boff, nBE, rowE, rowU, curE, curU);
    entpre_kernel<<<(NE + 31) / 32, 1024>>>(ent_real, ent_imag, fp_W1, rt_W1, Ah, At, P, NE);
    fill2_kernel<<<(E + EI + 255) / 256, 256>>>(eh, et, edge_type, curE, posE, tpackE, E,
                                                users, items, inter_edge_w, curU, posU,
                                                itemG, wG, EI);
    relpre_kernel<<<1, NR * 64>>>(rel_real, rel_imag, fp_W1, rt_W1, Arel, Prel, NR);
    gemm64_kernel<<<(NU + 15) / 16, 1024>>>(user_embed, Wq, userWq, NU);
    gemm64_kernel<<<(NI + 15) / 16, 1024>>>(item_embed, Wk, itemWk, NI);
    gemm64_kernel<<<(NI + 15) / 16, 1024>>>(item_embed, Wv, itemWv, NI);
    {
        long long th = (long long)EI * 16;
        score_kernel<<<(int)((th + 255) / 256), 256>>>(userWq, itemWk, users, items,
                                                       inter_edge_w, posU, scoresG, EI);
    }
    {
        long long th = (long long)NU * 32;
        usoftmax_kernel<<<(int)((th + 255) / 256), 256>>>(scoresG, itemG, rowU, itemCoeff, NU);
    }
    pref_kernel<<<256, 64>>>(itemCoeff, itemWv, pref, NI);
    qc_kernel<<<1, 64>>>(rt_W2, rt_b2, pref, qc);
    {
        long long th = (long long)E * 16;
        omega_kernel<<<(int)((th + 255) / 256), 256>>>(Ah, At, P, Arel, Prel, eh, et, edge_type,
                                                       fp_b1, fp_W2, fp_b2, rt_b1, qc, posE,
                                                       omegaG, NR, E);
    }
    alphaeta_kernel<<<(NE + 255) / 256, 256>>>(omegaG, rowE, alphaG, etaG, NE);

    const float* srcs[3] = {entity_emb, embA, embB};
    float* dsts[3] = {embA, embB, embA};
    const float* rhos[3] = {alphaG, alphaG, etaG};
    for (int hop = 0; hop < 3; hop++) {
        long long th = (long long)(NE + NU) * 16;
        hop_kernel<<<(int)((th + 255) / 256), 256>>>(
            srcs[hop], relation_emb, tpackE, rhos[hop], rowE, itemG, wG, rowU,
            dsts[hop], out, out + (size_t)NE * D, entity_emb, user_emb,
            (hop == 0) ? 1 : 0, NE, NU, NR);
    }
}